// round 12
// baseline (speedup 1.0000x reference)
#include <cuda_runtime.h>
#include <cuda_bf16.h>
#include <math.h>

#define BATCH   2
#define SEQ     2048
#define DMODEL  1024
#define NHEAD   16
#define HDIM    64
#define BH      (BATCH*NHEAD)      // 32
#define ROWS    (BATCH*SEQ)        // 4096
#define U_TOP   38                 // int(5 * ln(2048)) = 38
#define CCAP    192                // candidate buffer per row

typedef unsigned long long ull;

// ---- packed f32x2 helpers ---------------------------------------------------
__device__ __forceinline__ ull pk2(float x, float y) {
    ull r; asm("mov.b64 %0, {%1, %2};" : "=l"(r) : "f"(x), "f"(y)); return r;
}
__device__ __forceinline__ void ffma2(ull& d, ull a, ull b) {
    asm("fma.rn.f32x2 %0, %1, %2, %0;" : "+l"(d) : "l"(a), "l"(b));
}
__device__ __forceinline__ float2 up2(ull v) {
    float2 f; asm("mov.b64 {%0, %1}, %2;" : "=f"(f.x), "=f"(f.y) : "l"(v)); return f;
}
union f4u { float4 f; ull u[2]; };

// ---------------- scratch ----------------------------------------------------
__device__ __align__(256) float g_Q[ROWS * DMODEL];
__device__ __align__(256) float g_Kp[ROWS * DMODEL];
__device__ __align__(256) float g_Vp[ROWS * DMODEL];
__device__ __align__(256) float g_ctx[ROWS * DMODEL];
__device__ __align__(256) __nv_bfloat16 g_xh[ROWS * DMODEL],  g_xl[ROWS * DMODEL];
__device__ __align__(256) __nv_bfloat16 g_ch[ROWS * DMODEL],  g_cl[ROWS * DMODEL];
__device__ __align__(256) __nv_bfloat16 g_wvh[DMODEL*DMODEL], g_wvl[DMODEL*DMODEL];
__device__ __align__(256) __nv_bfloat16 g_woh[DMODEL*DMODEL], g_wol[DMODEL*DMODEL];

// =================== FFMA2 SGEMM, 16m x 8n, register-staged (R11, measured) ==
#define GBM 256
#define GBN 128
#define GBK 16
#define NKC (DMODEL / GBK)

__device__ __forceinline__
void gemm_body(const float* __restrict__ A, const float* __restrict__ Bw,
               const float* __restrict__ bias, float* __restrict__ C,
               int m0, int n0, int N)
{
    __shared__ float As[GBK][GBM];
    __shared__ float Bs[GBK][GBN];

    const int tid = threadIdx.x;
    const int tx = tid & 15;
    const int ty = tid >> 4;

    const int arow0 = tid >> 2,  akq = tid & 3;
    const int brow0 = tid >> 2,  bkq = tid & 3;

    ull acc2[8][8];
#pragma unroll
    for (int i = 0; i < 8; i++)
#pragma unroll
        for (int j = 0; j < 8; j++) acc2[i][j] = 0ull;

    float4 pa[4], pb[2];
#pragma unroll
    for (int i = 0; i < 4; i++)
        pa[i] = *(const float4*)(A + (size_t)(m0 + arow0 + i * 64) * DMODEL + akq * 4);
#pragma unroll
    for (int i = 0; i < 2; i++)
        pb[i] = *(const float4*)(Bw + (size_t)(n0 + brow0 + i * 64) * DMODEL + bkq * 4);

    for (int c = 0; c < NKC; c++) {
        __syncthreads();
#pragma unroll
        for (int i = 0; i < 4; i++) {
            int row = arow0 + i * 64;
            As[akq*4+0][row] = pa[i].x; As[akq*4+1][row] = pa[i].y;
            As[akq*4+2][row] = pa[i].z; As[akq*4+3][row] = pa[i].w;
        }
#pragma unroll
        for (int i = 0; i < 2; i++) {
            int row = brow0 + i * 64;
            Bs[bkq*4+0][row] = pb[i].x; Bs[bkq*4+1][row] = pb[i].y;
            Bs[bkq*4+2][row] = pb[i].z; Bs[bkq*4+3][row] = pb[i].w;
        }
        if (c + 1 < NKC) {
            const int k0 = (c + 1) * GBK;
#pragma unroll
            for (int i = 0; i < 4; i++)
                pa[i] = *(const float4*)(A + (size_t)(m0 + arow0 + i * 64) * DMODEL + k0 + akq * 4);
#pragma unroll
            for (int i = 0; i < 2; i++)
                pb[i] = *(const float4*)(Bw + (size_t)(n0 + brow0 + i * 64) * DMODEL + k0 + bkq * 4);
        }
        __syncthreads();

#pragma unroll
        for (int kk = 0; kk < GBK; kk++) {
            f4u a4[4];
#pragma unroll
            for (int q = 0; q < 4; q++)
                a4[q].f = *(float4*)&As[kk][ty * 16 + q * 4];
            float bf[8];
            *(float4*)&bf[0] = *(float4*)&Bs[kk][tx * 8];
            *(float4*)&bf[4] = *(float4*)&Bs[kk][tx * 8 + 4];
            ull bd[8];
#pragma unroll
            for (int j = 0; j < 8; j++) bd[j] = pk2(bf[j], bf[j]);
#pragma unroll
            for (int mp = 0; mp < 8; mp++) {
                ull ap = a4[mp >> 1].u[mp & 1];
#pragma unroll
                for (int j = 0; j < 8; j++) ffma2(acc2[mp][j], ap, bd[j]);
            }
        }
    }

    float bc[8];
#pragma unroll
    for (int j = 0; j < 8; j++) bc[j] = bias[n0 + tx * 8 + j];

#pragma unroll
    for (int mp = 0; mp < 8; mp++) {
        const int rowe = m0 + ty * 16 + mp * 2;
        float2 p[8];
#pragma unroll
        for (int j = 0; j < 8; j++) p[j] = up2(acc2[mp][j]);
        float4 e0 = make_float4(p[0].x + bc[0], p[1].x + bc[1], p[2].x + bc[2], p[3].x + bc[3]);
        float4 e1 = make_float4(p[4].x + bc[4], p[5].x + bc[5], p[6].x + bc[6], p[7].x + bc[7]);
        float4 o0 = make_float4(p[0].y + bc[0], p[1].y + bc[1], p[2].y + bc[2], p[3].y + bc[3]);
        float4 o1 = make_float4(p[4].y + bc[4], p[5].y + bc[5], p[6].y + bc[6], p[7].y + bc[7]);
        float* r0 = C + (size_t)rowe * N + n0 + tx * 8;
        float* r1 = C + (size_t)(rowe + 1) * N + n0 + tx * 8;
        *(float4*)(r0)     = e0;  *(float4*)(r0 + 4) = e1;
        *(float4*)(r1)     = o0;  *(float4*)(r1 + 4) = o1;
    }
}

__global__ __launch_bounds__(256)
void qk_gemm(const float* __restrict__ x,
             const float* __restrict__ Wq, const float* __restrict__ bq, float* __restrict__ Q,
             const float* __restrict__ Wk, const float* __restrict__ bk, float* __restrict__ K)
{
    const int sel = blockIdx.z;
    const float* W = (sel == 0) ? Wq : Wk;
    const float* b = (sel == 0) ? bq : bk;
    float*       C = (sel == 0) ? Q  : K;
    gemm_body(x, W, b, C, blockIdx.y * GBM, blockIdx.x * GBN, DMODEL);
}

// =================== HMMA helpers (V / out-proj: measured ~87us each) ========
__device__ __forceinline__ unsigned smem_u32(const void* p) {
    unsigned a;
    asm("{ .reg .u64 t; cvta.to.shared.u64 t, %1; cvt.u32.u64 %0, t; }"
        : "=r"(a) : "l"(p));
    return a;
}
__device__ __forceinline__ void ldsm_x4(unsigned* r, unsigned addr) {
    asm volatile("ldmatrix.sync.aligned.m8n8.x4.shared.b16 {%0,%1,%2,%3}, [%4];"
                 : "=r"(r[0]), "=r"(r[1]), "=r"(r[2]), "=r"(r[3]) : "r"(addr));
}
__device__ __forceinline__ void mma16816(float* c, const unsigned* a, const unsigned* b) {
    asm volatile("mma.sync.aligned.m16n8k16.row.col.f32.bf16.bf16.f32 "
                 "{%0,%1,%2,%3}, {%4,%5,%6,%7}, {%8,%9}, {%0,%1,%2,%3};"
                 : "+f"(c[0]), "+f"(c[1]), "+f"(c[2]), "+f"(c[3])
                 : "r"(a[0]), "r"(a[1]), "r"(a[2]), "r"(a[3]), "r"(b[0]), "r"(b[1]));
}
__device__ __forceinline__ void cp_async16(unsigned dst, const void* src) {
    asm volatile("cp.async.cg.shared.global [%0], [%1], 16;" :: "r"(dst), "l"(src));
}
#define CP_COMMIT() asm volatile("cp.async.commit_group;" ::: "memory")

__global__ __launch_bounds__(256)
void cvt_split(const float* __restrict__ src, __nv_bfloat16* __restrict__ hi,
               __nv_bfloat16* __restrict__ lo, int n4)
{
    int i = blockIdx.x * blockDim.x + threadIdx.x;
    for (; i < n4; i += gridDim.x * blockDim.x) {
        float4 v = *((const float4*)src + i);
        __nv_bfloat16 h0 = __float2bfloat16(v.x), h1 = __float2bfloat16(v.y);
        __nv_bfloat16 h2 = __float2bfloat16(v.z), h3 = __float2bfloat16(v.w);
        __nv_bfloat16 l0 = __float2bfloat16(v.x - __bfloat162float(h0));
        __nv_bfloat16 l1 = __float2bfloat16(v.y - __bfloat162float(h1));
        __nv_bfloat16 l2 = __float2bfloat16(v.z - __bfloat162float(h2));
        __nv_bfloat16 l3 = __float2bfloat16(v.w - __bfloat162float(h3));
        __nv_bfloat162 hh[2] = { {h0, h1}, {h2, h3} };
        __nv_bfloat162 ll[2] = { {l0, l1}, {l2, l3} };
        *((float2*)hi + i) = *(float2*)hh;
        *((float2*)lo + i) = *(float2*)ll;
    }
}

#define NCHUNK (DMODEL / 16)
#define ROWB   48
#define TILEB  (128 * ROWB)
#define STAGEB (4 * TILEB)

__device__ __forceinline__
void tc_gemm_body(const __nv_bfloat16* __restrict__ Ah, const __nv_bfloat16* __restrict__ Al,
                  const __nv_bfloat16* __restrict__ Bh, const __nv_bfloat16* __restrict__ Bl,
                  const float* __restrict__ bias, float* __restrict__ C,
                  int m0, int n0, int ldc)
{
    __shared__ __align__(16) char stage[2 * STAGEB];
    const unsigned sbase = smem_u32(stage);

    const int tid  = threadIdx.x;
    const int lane = tid & 31;
    const int wid  = tid >> 5;
    const int wm   = wid & 3;
    const int wn   = wid >> 2;

    const int lrow  = tid >> 1;
    const int lhalf = tid & 1;
    const __nv_bfloat16* gsrc[4] = {
        Ah + (size_t)(m0 + lrow) * DMODEL + lhalf * 8,
        Al + (size_t)(m0 + lrow) * DMODEL + lhalf * 8,
        Bh + (size_t)(n0 + lrow) * DMODEL + lhalf * 8,
        Bl + (size_t)(n0 + lrow) * DMODEL + lhalf * 8 };
    const unsigned sdst = sbase + lrow * ROWB + lhalf * 16;

    float acc[2][8][4];
#pragma unroll
    for (int i = 0; i < 2; i++)
#pragma unroll
        for (int j = 0; j < 8; j++)
#pragma unroll
            for (int k = 0; k < 4; k++) acc[i][j][k] = 0.f;

#pragma unroll
    for (int t = 0; t < 4; t++)
        cp_async16(sdst + t * TILEB, gsrc[t]);
    CP_COMMIT();

    const int arow = wm * 32 + (lane & 15);
    const unsigned a_off = arow * ROWB + (lane >> 4) * 16;
    const int brow = wn * 64 + ((lane >> 4) << 3) + (lane & 7);
    const unsigned b_off = brow * ROWB + ((lane >> 3) & 1) * 16;

    for (int c = 0; c < NCHUNK; c++) {
        if (c + 1 < NCHUNK) {
            const unsigned sd = sdst + ((c + 1) & 1) * STAGEB;
#pragma unroll
            for (int t = 0; t < 4; t++)
                cp_async16(sd + t * TILEB, gsrc[t] + (size_t)(c + 1) * 16);
            CP_COMMIT();
            asm volatile("cp.async.wait_group 1;" ::: "memory");
        } else {
            asm volatile("cp.async.wait_group 0;" ::: "memory");
        }
        __syncthreads();

        const unsigned sb = sbase + (c & 1) * STAGEB;
        unsigned ah[2][4], al[2][4];
#pragma unroll
        for (int mt = 0; mt < 2; mt++) {
            ldsm_x4(ah[mt], sb + 0 * TILEB + a_off + mt * 16 * ROWB);
            ldsm_x4(al[mt], sb + 1 * TILEB + a_off + mt * 16 * ROWB);
        }
#pragma unroll
        for (int p = 0; p < 4; p++) {
            unsigned bh4[4], bl4[4];
            ldsm_x4(bh4, sb + 2 * TILEB + b_off + p * 16 * ROWB);
            ldsm_x4(bl4, sb + 3 * TILEB + b_off + p * 16 * ROWB);
#pragma unroll
            for (int mt = 0; mt < 2; mt++) {
                mma16816(acc[mt][2*p+0], ah[mt], bh4 + 0);
                mma16816(acc[mt][2*p+0], ah[mt], bl4 + 0);
                mma16816(acc[mt][2*p+0], al[mt], bh4 + 0);
                mma16816(acc[mt][2*p+1], ah[mt], bh4 + 2);
                mma16816(acc[mt][2*p+1], ah[mt], bl4 + 2);
                mma16816(acc[mt][2*p+1], al[mt], bh4 + 2);
            }
        }
        __syncthreads();
    }

    const int g = lane >> 2, qd = lane & 3;
#pragma unroll
    for (int mt = 0; mt < 2; mt++) {
        const int rowg = m0 + wm * 32 + mt * 16 + g;
#pragma unroll
        for (int nt = 0; nt < 8; nt++) {
            const int colg = n0 + wn * 64 + nt * 8 + qd * 2;
            const float b0 = bias[colg], b1 = bias[colg + 1];
            float2 o0 = make_float2(acc[mt][nt][0] + b0, acc[mt][nt][1] + b1);
            float2 o1 = make_float2(acc[mt][nt][2] + b0, acc[mt][nt][3] + b1);
            *(float2*)(C + (size_t)rowg * ldc + colg)       = o0;
            *(float2*)(C + (size_t)(rowg + 8) * ldc + colg) = o1;
        }
    }
}

__global__ __launch_bounds__(256)
void tc_gemm1(const __nv_bfloat16* __restrict__ a0, const __nv_bfloat16* __restrict__ a1,
              const __nv_bfloat16* __restrict__ w0, const __nv_bfloat16* __restrict__ w1,
              const float* __restrict__ b, float* __restrict__ C)
{
    tc_gemm_body(a0, a1, w0, w1, b, C, blockIdx.y * 128, blockIdx.x * 128, DMODEL);
}

// ---------------- fused ProbSparse attention ---------------------------------
// 512 threads. Phase 1: 8q x 4k per thread, KT=1024 k-rows, d-chunks of 16
// floats, K staged through registers, pair-line conflict-free swizzle.
#define TQ 16
#define KT 1024
#define DC 16
#define ATHREADS 512
#define NCC 8               // (SEQ/KT=2 tiles) x (64/DC=4 d-chunks)

__device__ __forceinline__ unsigned fkey(float x) {
    unsigned u = __float_as_uint(x);
    return (u & 0x80000000u) ? ~u : (u | 0x80000000u);
}
__device__ __forceinline__ float unfkey(unsigned k) {
    unsigned u = (k & 0x80000000u) ? (k ^ 0x80000000u) : ~k;
    return __uint_as_float(u);
}

__device__ unsigned radix_select(const float* __restrict__ Srow,
                                 unsigned* __restrict__ myhist, int lane)
{
    unsigned prefix = 0;
    int remaining = U_TOP;
    for (int pass = 0; pass < 4; pass++) {
        const int shift = 24 - pass * 8;
#pragma unroll
        for (int j = 0; j < 8; j++) myhist[lane * 8 + j] = 0;
        __syncwarp();
        for (int i = lane; i < SEQ; i += 32) {
            unsigned key = fkey(Srow[i]);
            bool ok = (pass == 0) || ((key >> (shift + 8)) == prefix);
            if (ok) atomicAdd(&myhist[(key >> shift) & 255], 1u);
        }
        __syncwarp();
        unsigned psum = 0;
#pragma unroll
        for (int j = 0; j < 8; j++) psum += myhist[lane * 8 + j];
        unsigned c = psum;
#pragma unroll
        for (int off = 1; off < 32; off <<= 1) {
            unsigned o = __shfl_down_sync(0xffffffffu, c, off);
            if (lane + off < 32) c += o;
        }
        unsigned mk = __ballot_sync(0xffffffffu, c >= (unsigned)remaining);
        int lsel = 31 - __clz(mk);
        int digit = 0, newrem = remaining;
        if (lane == lsel) {
            unsigned cum = c - psum;
            for (int j = 7; j >= 0; j--) {
                unsigned hv = myhist[lsel * 8 + j];
                cum += hv;
                if (cum >= (unsigned)remaining) {
                    digit = lsel * 8 + j;
                    newrem = remaining - (int)(cum - hv);
                    break;
                }
            }
        }
        digit  = __shfl_sync(0xffffffffu, digit, lsel);
        newrem = __shfl_sync(0xffffffffu, newrem, lsel);
        prefix = (prefix << 8) | (unsigned)digit;
        remaining = newrem;
        __syncwarp();
    }
    return prefix;
}

// smem: S[16*2048] | Qs[16*64] | Ks[KT*DC floats, pair-line swizzled] | wbuf
#define ATTN_SMEM_BYTES ((TQ*SEQ + TQ*64 + KT*DC) * 4 + 16*384*4)

__global__ __launch_bounds__(ATHREADS)
void attn_kernel(const float* __restrict__ Q, const float* __restrict__ K,
                 const float* __restrict__ V, float* __restrict__ ctx)
{
    extern __shared__ char smraw[];
    float*    S    = (float*)smraw;
    float*    Qs   = S  + TQ * SEQ;
    float*    Ks   = Qs + TQ * 64;                 // 512 pair-lines x 32 floats
    unsigned* wbuf = (unsigned*)(Ks + KT * DC);    // 16 * 384

    const int tid = threadIdx.x;
    const int qt  = blockIdx.x;
    const int bh  = blockIdx.y;
    const int b   = bh >> 4, h = bh & 15;
    const int q0  = qt * TQ;

    const float* Qbase = Q + ((size_t)b * SEQ + q0) * DMODEL + h * HDIM;
    const float* Kbase = K + ((size_t)b * SEQ) * DMODEL + h * HDIM;
    const float* Vbase = V + ((size_t)b * SEQ) * DMODEL + h * HDIM;

    if (tid < 256) {
        int row = tid >> 4, c4 = tid & 15;
        *(float4*)(Qs + row * 64 + c4 * 4) =
            *(const float4*)(Qbase + (size_t)row * DMODEL + c4 * 4);
    }

    // ---- phase 1: scores, 8q x 4k per thread ----
    const int kq  = tid & 255;     // k-group: tile rows 4kq..4kq+3
    const int qg  = tid >> 8;      // 0..1: q rows qg*8..qg*8+7
    const int swz = kq & 7;

    const int row_l = tid >> 2;    // loader row (+128*i)
    const int d4_l  = tid & 3;     // loader chunk-f4
    const int skey  = ((row_l >> 2) & 7);          // (r>>2)&7, i-invariant
    const int sslot0 = (d4_l + ((row_l & 1) << 2)) ^ skey;

    float4 st[8];
    // prefetch cc=0 (kt 0, d-chunk 0)
#pragma unroll
    for (int i = 0; i < 8; i++)
        st[i] = *(const float4*)(Kbase + (size_t)(row_l + i * 128) * DMODEL + d4_l * 4);

    ull acc2[8][4];

    for (int cc = 0; cc < NCC; cc++) {
        const int ch = cc & 3;          // d-chunk 0..3 (16 floats each)
        const int kb = (cc >> 2) * KT;  // k-tile base

        __syncthreads();
        // store staged regs: element (row r, f4 d) -> line r>>1, slot (d+(r&1)*4)^((r>>2)&7)
#pragma unroll
        for (int i = 0; i < 8; i++) {
            int r = row_l + i * 128;
            *(float4*)(Ks + (r >> 1) * 32 + (sslot0 << 2)) = st[i];
        }
        if (cc + 1 < NCC) {
            const int nch = (cc + 1) & 3;
            const int nkb = ((cc + 1) >> 2) * KT;
#pragma unroll
            for (int i = 0; i < 8; i++)
                st[i] = *(const float4*)(Kbase + (size_t)(nkb + row_l + i * 128) * DMODEL
                                         + nch * DC + d4_l * 4);
        }
        __syncthreads();

        if (ch == 0) {
#pragma unroll
            for (int j = 0; j < 8; j++)
#pragma unroll
                for (int i = 0; i < 4; i++) acc2[j][i] = 0ull;
        }

#pragma unroll
        for (int d4 = 0; d4 < 4; d4++) {
            f4u kv[4];
#pragma unroll
            for (int i = 0; i < 4; i++) {
                const int line = 2 * kq + (i >> 1);
                const int slot = (d4 + ((i & 1) << 2)) ^ swz;
                kv[i].f = *(float4*)(Ks + line * 32 + (slot << 2));
            }
#pragma unroll
            for (int j = 0; j < 8; j++) {
                f4u qv;
                qv.f = *(float4*)(Qs + (qg * 8 + j) * 64 + ch * DC + (d4 << 2));
#pragma unroll
                for (int i = 0; i < 4; i++) {
                    ffma2(acc2[j][i], qv.u[0], kv[i].u[0]);
                    ffma2(acc2[j][i], qv.u[1], kv[i].u[1]);
                }
            }
        }

        if (ch == 3) {     // all 4 d-chunks done: flush scores
#pragma unroll
            for (int j = 0; j < 8; j++) {
                float2 r0 = up2(acc2[j][0]), r1 = up2(acc2[j][1]);
                float2 r2 = up2(acc2[j][2]), r3 = up2(acc2[j][3]);
                float4 o = make_float4((r0.x + r0.y) * 0.125f, (r1.x + r1.y) * 0.125f,
                                       (r2.x + r2.y) * 0.125f, (r3.x + r3.y) * 0.125f);
                *(float4*)(S + (size_t)(qg * 8 + j) * SEQ + kb + kq * 4) = o;
            }
        }
    }
    __syncthreads();

    // ---- phase 2: 1 row per warp, float4 scans (R11, measured neutral) ----
    const int lane = tid & 31, wid = tid >> 5;
    const unsigned lmlt = (1u << lane) - 1u;
    unsigned* chk = wbuf + wid * 384;
    int*      chi = (int*)(chk + CCAP);
    unsigned* myhist = chk;

    {
        const int q = wid;
        const float* Srow = S + (size_t)q * SEQ;

        float lm = -1e30f;
        for (int i = lane; i < SEQ / 4; i += 32) {
            float4 v = ((const float4*)Srow)[i];
            lm = fmaxf(lm, fmaxf(fmaxf(v.x, v.y), fmaxf(v.z, v.w)));
        }
        float m = lm, tmin = lm;
#pragma unroll
        for (int off = 16; off; off >>= 1) {
            m    = fmaxf(m,    __shfl_xor_sync(0xffffffffu, m,    off));
            tmin = fminf(tmin, __shfl_xor_sync(0xffffffffu, tmin, off));
        }
        const unsigned Tk = fkey(tmin);

        int cnt = 0;
        for (int base = 0; base < SEQ; base += 128) {
            float4 v = *(const float4*)(Srow + base + lane * 4);
            unsigned k4[4] = { fkey(v.x), fkey(v.y), fkey(v.z), fkey(v.w) };
#pragma unroll
            for (int c = 0; c < 4; c++) {
                bool kp = k4[c] >= Tk;
                unsigned bm = __ballot_sync(0xffffffffu, kp);
                if (kp) {
                    int pos = cnt + __popc(bm & lmlt);
                    if (pos < CCAP) { chk[pos] = k4[c]; chi[pos] = base + lane * 4 + c; }
                }
                cnt += __popc(bm);
            }
        }
        __syncwarp();

        const bool okc = (cnt >= U_TOP && cnt <= CCAP);
        unsigned kth;
        if (okc) {
            unsigned ck[6];
#pragma unroll
            for (int t = 0; t < 6; t++) {
                int p = lane + t * 32;
                ck[t] = (p < cnt) ? chk[p] : 0u;
            }
            unsigned lo = Tk, hi = fkey(m);
            while (lo < hi) {
                unsigned mid = lo + ((hi - lo + 1) >> 1);
                int c = 0;
#pragma unroll
                for (int t = 0; t < 6; t++) c += (ck[t] >= mid) ? 1 : 0;
                c = __reduce_add_sync(0xffffffffu, c);
                if (c >= U_TOP) lo = mid; else hi = mid - 1;
            }
            kth = lo;
        } else {
            kth = radix_select(Srow, myhist, lane);
        }

        float lsum = 0.f;
        int nk = 0;
        if (okc) {
            for (int base = 0; base < cnt; base += 32) {
                int p = base + lane;
                unsigned key = (p < cnt) ? chk[p] : 0u;
                int idx      = (p < cnt) ? chi[p] : 0;
                __syncwarp();
                bool kp = (p < cnt) && (key >= kth);
                unsigned bm = __ballot_sync(0xffffffffu, kp);
                if (kp) {
                    float w = __expf(unfkey(key) - m);
                    lsum += w;
                    int pos = nk + __popc(bm & lmlt);
                    chi[pos] = idx;
                    chk[pos] = __float_as_uint(w);
                }
                nk += __popc(bm);
            }
        } else {
            for (int base = 0; base < SEQ; base += 32) {
                int i = base + lane;
                float s = Srow[i];
                bool kp = fkey(s) >= kth;
                unsigned bm = __ballot_sync(0xffffffffu, kp);
                if (kp) {
                    float w = __expf(s - m);
                    lsum += w;
                    int pos = nk + __popc(bm & lmlt);
                    if (pos < CCAP) { chi[pos] = i; chk[pos] = __float_as_uint(w); }
                }
                nk += __popc(bm);
            }
        }
        __syncwarp();
#pragma unroll
        for (int off = 16; off; off >>= 1)
            lsum += __shfl_xor_sync(0xffffffffu, lsum, off);
        const float scale = 1.f / lsum;

        float c0 = 0.f, c1 = 0.f;
        if (nk <= CCAP) {
#pragma unroll 4
            for (int j = 0; j < nk; j++) {
                int kkidx = chi[j];
                float w = __uint_as_float(chk[j]);
                const float* vr = Vbase + (size_t)kkidx * DMODEL;
                c0 += w * vr[lane];
                c1 += w * vr[lane + 32];
            }
        } else {
            for (int i = 0; i < SEQ; i++) {
                float s = Srow[i];
                if (fkey(s) >= kth) {
                    float w = __expf(s - m);
                    const float* vr = Vbase + (size_t)i * DMODEL;
                    c0 += w * vr[lane];
                    c1 += w * vr[lane + 32];
                }
            }
        }
        float* orow = ctx + ((size_t)b * SEQ + q0 + q) * DMODEL + h * HDIM;
        orow[lane]      = c0 * scale;
        orow[lane + 32] = c1 * scale;
    }
}

// ---------------- launch ----------------------------------------------------
extern "C" void kernel_launch(void* const* d_in, const int* in_sizes, int n_in,
                              void* d_out, int out_size)
{
    const float* x  = (const float*)d_in[0];
    const float* Wq = (const float*)d_in[1];
    const float* bq = (const float*)d_in[2];
    const float* Wk = (const float*)d_in[3];
    const float* bk = (const float*)d_in[4];
    const float* Wv = (const float*)d_in[5];
    const float* bv = (const float*)d_in[6];
    const float* Wo = (const float*)d_in[7];
    const float* bo = (const float*)d_in[8];
    float* out = (float*)d_out;

    float *Q, *K, *V, *C;
    cudaGetSymbolAddress((void**)&Q, g_Q);
    cudaGetSymbolAddress((void**)&K, g_Kp);
    cudaGetSymbolAddress((void**)&V, g_Vp);
    cudaGetSymbolAddress((void**)&C, g_ctx);
    __nv_bfloat16 *xh,*xl,*ch,*cl,*wvh,*wvl,*woh,*wol;
    cudaGetSymbolAddress((void**)&xh, g_xh);   cudaGetSymbolAddress((void**)&xl, g_xl);
    cudaGetSymbolAddress((void**)&ch, g_ch);   cudaGetSymbolAddress((void**)&cl, g_cl);
    cudaGetSymbolAddress((void**)&wvh, g_wvh); cudaGetSymbolAddress((void**)&wvl, g_wvl);
    cudaGetSymbolAddress((void**)&woh, g_woh); cudaGetSymbolAddress((void**)&wol, g_wol);

    // Q,K: exact fp32 FFMA2 pipelined path (selection-critical)
    qk_gemm<<<dim3(DMODEL / GBN, ROWS / GBM, 2), 256>>>(x, Wq, bq, Q, Wk, bk, K);

    // V: HMMA bf16x3 (precision-insensitive, measured fast)
    cvt_split<<<1024, 256>>>(x,  xh,  xl,  ROWS*DMODEL/4);
    cvt_split<<<512, 256>>>(Wv, wvh, wvl, DMODEL*DMODEL/4);
    cvt_split<<<512, 256>>>(Wo, woh, wol, DMODEL*DMODEL/4);
    tc_gemm1<<<dim3(DMODEL/128, ROWS/128), 256>>>(xh, xl, wvh, wvl, bv, V);

    cudaFuncSetAttribute(attn_kernel, cudaFuncAttributeMaxDynamicSharedMemorySize,
                         ATTN_SMEM_BYTES);
    attn_kernel<<<dim3(SEQ / TQ, BH), ATHREADS, ATTN_SMEM_BYTES>>>(Q, K, V, C);

    cvt_split<<<1024, 256>>>(C, ch, cl, ROWS*DMODEL/4);
    tc_gemm1<<<dim3(DMODEL/128, ROWS/128), 256>>>(ch, cl, woh, wol, bo, out);
}

// round 13
// speedup vs baseline: 1.1192x; 1.1192x over previous
#include <cuda_runtime.h>
#include <cuda_bf16.h>
#include <math.h>

#define BATCH   2
#define SEQ     2048
#define DMODEL  1024
#define NHEAD   16
#define HDIM    64
#define BH      (BATCH*NHEAD)      // 32
#define ROWS    (BATCH*SEQ)        // 4096
#define U_TOP   38                 // int(5 * ln(2048)) = 38
#define CCAP    192                // candidate buffer per row

typedef unsigned long long ull;

// ---- packed f32x2 helpers ---------------------------------------------------
__device__ __forceinline__ ull pk2(float x, float y) {
    ull r; asm("mov.b64 %0, {%1, %2};" : "=l"(r) : "f"(x), "f"(y)); return r;
}
__device__ __forceinline__ void ffma2(ull& d, ull a, ull b) {
    asm("fma.rn.f32x2 %0, %1, %2, %0;" : "+l"(d) : "l"(a), "l"(b));
}
__device__ __forceinline__ float2 up2(ull v) {
    float2 f; asm("mov.b64 {%0, %1}, %2;" : "=f"(f.x), "=f"(f.y) : "l"(v)); return f;
}
union f4u { float4 f; ull u[2]; };

// ---------------- scratch ----------------------------------------------------
__device__ __align__(256) float g_Q[ROWS * DMODEL];
__device__ __align__(256) float g_Kp[ROWS * DMODEL];
__device__ __align__(256) float g_Vp[ROWS * DMODEL];
__device__ __align__(256) float g_ctx[ROWS * DMODEL];
__device__ __align__(256) __nv_bfloat16 g_xh[ROWS * DMODEL],  g_xl[ROWS * DMODEL];
__device__ __align__(256) __nv_bfloat16 g_ch[ROWS * DMODEL],  g_cl[ROWS * DMODEL];
__device__ __align__(256) __nv_bfloat16 g_wvh[DMODEL*DMODEL], g_wvl[DMODEL*DMODEL];
__device__ __align__(256) __nv_bfloat16 g_woh[DMODEL*DMODEL], g_wol[DMODEL*DMODEL];

// =================== FFMA2 SGEMM, 16m x 8n, register-staged (R11, measured) ==
#define GBM 256
#define GBN 128
#define GBK 16
#define NKC (DMODEL / GBK)

__device__ __forceinline__
void gemm_body(const float* __restrict__ A, const float* __restrict__ Bw,
               const float* __restrict__ bias, float* __restrict__ C,
               int m0, int n0, int N)
{
    __shared__ float As[GBK][GBM];
    __shared__ float Bs[GBK][GBN];

    const int tid = threadIdx.x;
    const int tx = tid & 15;
    const int ty = tid >> 4;

    const int arow0 = tid >> 2,  akq = tid & 3;
    const int brow0 = tid >> 2,  bkq = tid & 3;

    ull acc2[8][8];
#pragma unroll
    for (int i = 0; i < 8; i++)
#pragma unroll
        for (int j = 0; j < 8; j++) acc2[i][j] = 0ull;

    float4 pa[4], pb[2];
#pragma unroll
    for (int i = 0; i < 4; i++)
        pa[i] = *(const float4*)(A + (size_t)(m0 + arow0 + i * 64) * DMODEL + akq * 4);
#pragma unroll
    for (int i = 0; i < 2; i++)
        pb[i] = *(const float4*)(Bw + (size_t)(n0 + brow0 + i * 64) * DMODEL + bkq * 4);

    for (int c = 0; c < NKC; c++) {
        __syncthreads();
#pragma unroll
        for (int i = 0; i < 4; i++) {
            int row = arow0 + i * 64;
            As[akq*4+0][row] = pa[i].x; As[akq*4+1][row] = pa[i].y;
            As[akq*4+2][row] = pa[i].z; As[akq*4+3][row] = pa[i].w;
        }
#pragma unroll
        for (int i = 0; i < 2; i++) {
            int row = brow0 + i * 64;
            Bs[bkq*4+0][row] = pb[i].x; Bs[bkq*4+1][row] = pb[i].y;
            Bs[bkq*4+2][row] = pb[i].z; Bs[bkq*4+3][row] = pb[i].w;
        }
        if (c + 1 < NKC) {
            const int k0 = (c + 1) * GBK;
#pragma unroll
            for (int i = 0; i < 4; i++)
                pa[i] = *(const float4*)(A + (size_t)(m0 + arow0 + i * 64) * DMODEL + k0 + akq * 4);
#pragma unroll
            for (int i = 0; i < 2; i++)
                pb[i] = *(const float4*)(Bw + (size_t)(n0 + brow0 + i * 64) * DMODEL + k0 + bkq * 4);
        }
        __syncthreads();

#pragma unroll
        for (int kk = 0; kk < GBK; kk++) {
            f4u a4[4];
#pragma unroll
            for (int q = 0; q < 4; q++)
                a4[q].f = *(float4*)&As[kk][ty * 16 + q * 4];
            float bf[8];
            *(float4*)&bf[0] = *(float4*)&Bs[kk][tx * 8];
            *(float4*)&bf[4] = *(float4*)&Bs[kk][tx * 8 + 4];
            ull bd[8];
#pragma unroll
            for (int j = 0; j < 8; j++) bd[j] = pk2(bf[j], bf[j]);
#pragma unroll
            for (int mp = 0; mp < 8; mp++) {
                ull ap = a4[mp >> 1].u[mp & 1];
#pragma unroll
                for (int j = 0; j < 8; j++) ffma2(acc2[mp][j], ap, bd[j]);
            }
        }
    }

    float bc[8];
#pragma unroll
    for (int j = 0; j < 8; j++) bc[j] = bias[n0 + tx * 8 + j];

#pragma unroll
    for (int mp = 0; mp < 8; mp++) {
        const int rowe = m0 + ty * 16 + mp * 2;
        float2 p[8];
#pragma unroll
        for (int j = 0; j < 8; j++) p[j] = up2(acc2[mp][j]);
        float4 e0 = make_float4(p[0].x + bc[0], p[1].x + bc[1], p[2].x + bc[2], p[3].x + bc[3]);
        float4 e1 = make_float4(p[4].x + bc[4], p[5].x + bc[5], p[6].x + bc[6], p[7].x + bc[7]);
        float4 o0 = make_float4(p[0].y + bc[0], p[1].y + bc[1], p[2].y + bc[2], p[3].y + bc[3]);
        float4 o1 = make_float4(p[4].y + bc[4], p[5].y + bc[5], p[6].y + bc[6], p[7].y + bc[7]);
        float* r0 = C + (size_t)rowe * N + n0 + tx * 8;
        float* r1 = C + (size_t)(rowe + 1) * N + n0 + tx * 8;
        *(float4*)(r0)     = e0;  *(float4*)(r0 + 4) = e1;
        *(float4*)(r1)     = o0;  *(float4*)(r1 + 4) = o1;
    }
}

__global__ __launch_bounds__(256)
void qk_gemm(const float* __restrict__ x,
             const float* __restrict__ Wq, const float* __restrict__ bq, float* __restrict__ Q,
             const float* __restrict__ Wk, const float* __restrict__ bk, float* __restrict__ K)
{
    const int sel = blockIdx.z;
    const float* W = (sel == 0) ? Wq : Wk;
    const float* b = (sel == 0) ? bq : bk;
    float*       C = (sel == 0) ? Q  : K;
    gemm_body(x, W, b, C, blockIdx.y * GBM, blockIdx.x * GBN, DMODEL);
}

// =================== HMMA helpers (V / out-proj: measured ~87us each) ========
__device__ __forceinline__ unsigned smem_u32(const void* p) {
    unsigned a;
    asm("{ .reg .u64 t; cvta.to.shared.u64 t, %1; cvt.u32.u64 %0, t; }"
        : "=r"(a) : "l"(p));
    return a;
}
__device__ __forceinline__ void ldsm_x4(unsigned* r, unsigned addr) {
    asm volatile("ldmatrix.sync.aligned.m8n8.x4.shared.b16 {%0,%1,%2,%3}, [%4];"
                 : "=r"(r[0]), "=r"(r[1]), "=r"(r[2]), "=r"(r[3]) : "r"(addr));
}
__device__ __forceinline__ void mma16816(float* c, const unsigned* a, const unsigned* b) {
    asm volatile("mma.sync.aligned.m16n8k16.row.col.f32.bf16.bf16.f32 "
                 "{%0,%1,%2,%3}, {%4,%5,%6,%7}, {%8,%9}, {%0,%1,%2,%3};"
                 : "+f"(c[0]), "+f"(c[1]), "+f"(c[2]), "+f"(c[3])
                 : "r"(a[0]), "r"(a[1]), "r"(a[2]), "r"(a[3]), "r"(b[0]), "r"(b[1]));
}
__device__ __forceinline__ void cp_async16(unsigned dst, const void* src) {
    asm volatile("cp.async.cg.shared.global [%0], [%1], 16;" :: "r"(dst), "l"(src));
}
#define CP_COMMIT() asm volatile("cp.async.commit_group;" ::: "memory")

__global__ __launch_bounds__(256)
void cvt_split(const float* __restrict__ src, __nv_bfloat16* __restrict__ hi,
               __nv_bfloat16* __restrict__ lo, int n4)
{
    int i = blockIdx.x * blockDim.x + threadIdx.x;
    for (; i < n4; i += gridDim.x * blockDim.x) {
        float4 v = *((const float4*)src + i);
        __nv_bfloat16 h0 = __float2bfloat16(v.x), h1 = __float2bfloat16(v.y);
        __nv_bfloat16 h2 = __float2bfloat16(v.z), h3 = __float2bfloat16(v.w);
        __nv_bfloat16 l0 = __float2bfloat16(v.x - __bfloat162float(h0));
        __nv_bfloat16 l1 = __float2bfloat16(v.y - __bfloat162float(h1));
        __nv_bfloat16 l2 = __float2bfloat16(v.z - __bfloat162float(h2));
        __nv_bfloat16 l3 = __float2bfloat16(v.w - __bfloat162float(h3));
        __nv_bfloat162 hh[2] = { {h0, h1}, {h2, h3} };
        __nv_bfloat162 ll[2] = { {l0, l1}, {l2, l3} };
        *((float2*)hi + i) = *(float2*)hh;
        *((float2*)lo + i) = *(float2*)ll;
    }
}

#define NCHUNK (DMODEL / 16)
#define ROWB   48
#define TILEB  (128 * ROWB)
#define STAGEB (4 * TILEB)

__device__ __forceinline__
void tc_gemm_body(const __nv_bfloat16* __restrict__ Ah, const __nv_bfloat16* __restrict__ Al,
                  const __nv_bfloat16* __restrict__ Bh, const __nv_bfloat16* __restrict__ Bl,
                  const float* __restrict__ bias, float* __restrict__ C,
                  int m0, int n0, int ldc)
{
    __shared__ __align__(16) char stage[2 * STAGEB];
    const unsigned sbase = smem_u32(stage);

    const int tid  = threadIdx.x;
    const int lane = tid & 31;
    const int wid  = tid >> 5;
    const int wm   = wid & 3;
    const int wn   = wid >> 2;

    const int lrow  = tid >> 1;
    const int lhalf = tid & 1;
    const __nv_bfloat16* gsrc[4] = {
        Ah + (size_t)(m0 + lrow) * DMODEL + lhalf * 8,
        Al + (size_t)(m0 + lrow) * DMODEL + lhalf * 8,
        Bh + (size_t)(n0 + lrow) * DMODEL + lhalf * 8,
        Bl + (size_t)(n0 + lrow) * DMODEL + lhalf * 8 };
    const unsigned sdst = sbase + lrow * ROWB + lhalf * 16;

    float acc[2][8][4];
#pragma unroll
    for (int i = 0; i < 2; i++)
#pragma unroll
        for (int j = 0; j < 8; j++)
#pragma unroll
            for (int k = 0; k < 4; k++) acc[i][j][k] = 0.f;

#pragma unroll
    for (int t = 0; t < 4; t++)
        cp_async16(sdst + t * TILEB, gsrc[t]);
    CP_COMMIT();

    const int arow = wm * 32 + (lane & 15);
    const unsigned a_off = arow * ROWB + (lane >> 4) * 16;
    const int brow = wn * 64 + ((lane >> 4) << 3) + (lane & 7);
    const unsigned b_off = brow * ROWB + ((lane >> 3) & 1) * 16;

    for (int c = 0; c < NCHUNK; c++) {
        if (c + 1 < NCHUNK) {
            const unsigned sd = sdst + ((c + 1) & 1) * STAGEB;
#pragma unroll
            for (int t = 0; t < 4; t++)
                cp_async16(sd + t * TILEB, gsrc[t] + (size_t)(c + 1) * 16);
            CP_COMMIT();
            asm volatile("cp.async.wait_group 1;" ::: "memory");
        } else {
            asm volatile("cp.async.wait_group 0;" ::: "memory");
        }
        __syncthreads();

        const unsigned sb = sbase + (c & 1) * STAGEB;
        unsigned ah[2][4], al[2][4];
#pragma unroll
        for (int mt = 0; mt < 2; mt++) {
            ldsm_x4(ah[mt], sb + 0 * TILEB + a_off + mt * 16 * ROWB);
            ldsm_x4(al[mt], sb + 1 * TILEB + a_off + mt * 16 * ROWB);
        }
#pragma unroll
        for (int p = 0; p < 4; p++) {
            unsigned bh4[4], bl4[4];
            ldsm_x4(bh4, sb + 2 * TILEB + b_off + p * 16 * ROWB);
            ldsm_x4(bl4, sb + 3 * TILEB + b_off + p * 16 * ROWB);
#pragma unroll
            for (int mt = 0; mt < 2; mt++) {
                mma16816(acc[mt][2*p+0], ah[mt], bh4 + 0);
                mma16816(acc[mt][2*p+0], ah[mt], bl4 + 0);
                mma16816(acc[mt][2*p+0], al[mt], bh4 + 0);
                mma16816(acc[mt][2*p+1], ah[mt], bh4 + 2);
                mma16816(acc[mt][2*p+1], ah[mt], bl4 + 2);
                mma16816(acc[mt][2*p+1], al[mt], bh4 + 2);
            }
        }
        __syncthreads();
    }

    const int g = lane >> 2, qd = lane & 3;
#pragma unroll
    for (int mt = 0; mt < 2; mt++) {
        const int rowg = m0 + wm * 32 + mt * 16 + g;
#pragma unroll
        for (int nt = 0; nt < 8; nt++) {
            const int colg = n0 + wn * 64 + nt * 8 + qd * 2;
            const float b0 = bias[colg], b1 = bias[colg + 1];
            float2 o0 = make_float2(acc[mt][nt][0] + b0, acc[mt][nt][1] + b1);
            float2 o1 = make_float2(acc[mt][nt][2] + b0, acc[mt][nt][3] + b1);
            *(float2*)(C + (size_t)rowg * ldc + colg)       = o0;
            *(float2*)(C + (size_t)(rowg + 8) * ldc + colg) = o1;
        }
    }
}

__global__ __launch_bounds__(256)
void tc_gemm1(const __nv_bfloat16* __restrict__ a0, const __nv_bfloat16* __restrict__ a1,
              const __nv_bfloat16* __restrict__ w0, const __nv_bfloat16* __restrict__ w1,
              const float* __restrict__ b, float* __restrict__ C)
{
    tc_gemm_body(a0, a1, w0, w1, b, C, blockIdx.y * 128, blockIdx.x * 128, DMODEL);
}

// ---------------- fused ProbSparse attention (R8 verbatim, measured) --------
#define TQ 16
#define KT 512
#define ATHREADS 512
#define NCC (SEQ / KT * 2)          // 8 chunk-iterations

__device__ __forceinline__ unsigned fkey(float x) {
    unsigned u = __float_as_uint(x);
    return (u & 0x80000000u) ? ~u : (u | 0x80000000u);
}
__device__ __forceinline__ float unfkey(unsigned k) {
    unsigned u = (k & 0x80000000u) ? (k ^ 0x80000000u) : ~k;
    return __uint_as_float(u);
}

__device__ unsigned radix_select(const float* __restrict__ Srow,
                                 unsigned* __restrict__ myhist, int lane)
{
    unsigned prefix = 0;
    int remaining = U_TOP;
    for (int pass = 0; pass < 4; pass++) {
        const int shift = 24 - pass * 8;
#pragma unroll
        for (int j = 0; j < 8; j++) myhist[lane * 8 + j] = 0;
        __syncwarp();
        for (int i = lane; i < SEQ; i += 32) {
            unsigned key = fkey(Srow[i]);
            bool ok = (pass == 0) || ((key >> (shift + 8)) == prefix);
            if (ok) atomicAdd(&myhist[(key >> shift) & 255], 1u);
        }
        __syncwarp();
        unsigned psum = 0;
#pragma unroll
        for (int j = 0; j < 8; j++) psum += myhist[lane * 8 + j];
        unsigned c = psum;
#pragma unroll
        for (int off = 1; off < 32; off <<= 1) {
            unsigned o = __shfl_down_sync(0xffffffffu, c, off);
            if (lane + off < 32) c += o;
        }
        unsigned mk = __ballot_sync(0xffffffffu, c >= (unsigned)remaining);
        int lsel = 31 - __clz(mk);
        int digit = 0, newrem = remaining;
        if (lane == lsel) {
            unsigned cum = c - psum;
            for (int j = 7; j >= 0; j--) {
                unsigned hv = myhist[lsel * 8 + j];
                cum += hv;
                if (cum >= (unsigned)remaining) {
                    digit = lsel * 8 + j;
                    newrem = remaining - (int)(cum - hv);
                    break;
                }
            }
        }
        digit  = __shfl_sync(0xffffffffu, digit, lsel);
        newrem = __shfl_sync(0xffffffffu, newrem, lsel);
        prefix = (prefix << 8) | (unsigned)digit;
        remaining = newrem;
        __syncwarp();
    }
    return prefix;
}

// smem: S[16*2048] | Qs[16*64] | Ks[512*32 swizzled] | wbuf[16 warps * 384 u32]
#define ATTN_SMEM_BYTES ((TQ*SEQ + TQ*64 + KT*32) * 4 + 16*384*4)

__global__ __launch_bounds__(ATHREADS)
void attn_kernel(const float* __restrict__ Q, const float* __restrict__ K,
                 const float* __restrict__ V, float* __restrict__ ctx)
{
    extern __shared__ char smraw[];
    float*    S    = (float*)smraw;
    float*    Qs   = S  + TQ * SEQ;
    float*    Ks   = Qs + TQ * 64;                 // 512 rows x 32 floats, swizzled
    unsigned* wbuf = (unsigned*)(Ks + KT * 32);    // 16 * 384

    const int tid = threadIdx.x;
    const int qt  = blockIdx.x;
    const int bh  = blockIdx.y;
    const int b   = bh >> 4, h = bh & 15;
    const int q0  = qt * TQ;

    const float* Qbase = Q + ((size_t)b * SEQ + q0) * DMODEL + h * HDIM;
    const float* Kbase = K + ((size_t)b * SEQ) * DMODEL + h * HDIM;
    const float* Vbase = V + ((size_t)b * SEQ) * DMODEL + h * HDIM;

    if (tid < 256) {
        int row = tid >> 4, c4 = tid & 15;
        *(float4*)(Qs + row * 64 + c4 * 4) =
            *(const float4*)(Qbase + (size_t)row * DMODEL + c4 * 4);
    }

    // ---- phase 1: scores, 4q x 4k per thread ----
    const int kq  = tid & 127;
    const int qg  = tid >> 7;
    const int swz = kq & 7;

    const int prow = tid >> 3;
    const int pd4  = tid & 7;

    float4 st[8];
#pragma unroll
    for (int i = 0; i < 8; i++) {
        int row = i * 64 + prow;
        st[i] = *(const float4*)(Kbase + (size_t)row * DMODEL + pd4 * 4);
    }

    ull acc2[4][4];

    for (int cc = 0; cc < NCC; cc++) {
        const int ch = cc & 1;
        const int kb = (cc >> 1) * KT;

        __syncthreads();
#pragma unroll
        for (int i = 0; i < 8; i++) {
            int row = i * 64 + prow;
            *(float4*)(Ks + row * 32 + ((pd4 ^ ((row >> 2) & 7)) << 2)) = st[i];
        }
        if (cc + 1 < NCC) {
            const int nch = (cc + 1) & 1;
            const int nkb = ((cc + 1) >> 1) * KT;
#pragma unroll
            for (int i = 0; i < 8; i++) {
                int row = i * 64 + prow;
                st[i] = *(const float4*)(Kbase + (size_t)(nkb + row) * DMODEL
                                         + nch * 32 + pd4 * 4);
            }
        }
        __syncthreads();

        if (ch == 0) {
#pragma unroll
            for (int j = 0; j < 4; j++)
#pragma unroll
                for (int i = 0; i < 4; i++) acc2[j][i] = 0ull;
        }

#pragma unroll
        for (int d4 = 0; d4 < 8; d4++) {
            f4u kv[4];
#pragma unroll
            for (int i = 0; i < 4; i++)
                kv[i].f = *(float4*)(Ks + (kq * 4 + i) * 32 + ((d4 ^ swz) << 2));
#pragma unroll
            for (int j = 0; j < 4; j++) {
                f4u qv;
                qv.f = *(float4*)(Qs + (qg * 4 + j) * 64 + ch * 32 + (d4 << 2));
#pragma unroll
                for (int i = 0; i < 4; i++) {
                    ffma2(acc2[j][i], qv.u[0], kv[i].u[0]);
                    ffma2(acc2[j][i], qv.u[1], kv[i].u[1]);
                }
            }
        }

        if (ch == 1) {
#pragma unroll
            for (int j = 0; j < 4; j++) {
                float2 r0 = up2(acc2[j][0]), r1 = up2(acc2[j][1]);
                float2 r2 = up2(acc2[j][2]), r3 = up2(acc2[j][3]);
                float4 o = make_float4((r0.x + r0.y) * 0.125f, (r1.x + r1.y) * 0.125f,
                                       (r2.x + r2.y) * 0.125f, (r3.x + r3.y) * 0.125f);
                *(float4*)(S + (size_t)(qg * 4 + j) * SEQ + kb + kq * 4) = o;
            }
        }
    }
    __syncthreads();

    // ---- phase 2: 1 row per warp ----
    const int lane = tid & 31, wid = tid >> 5;
    const unsigned lmlt = (1u << lane) - 1u;
    unsigned* chk = wbuf + wid * 384;
    int*      chi = (int*)(chk + CCAP);
    unsigned* myhist = chk;

    {
        const int q = wid;
        const float* Srow = S + (size_t)q * SEQ;

        float lm = -1e30f;
        for (int i = lane; i < SEQ; i += 32) lm = fmaxf(lm, Srow[i]);
        float m = lm, tmin = lm;
#pragma unroll
        for (int off = 16; off; off >>= 1) {
            m    = fmaxf(m,    __shfl_xor_sync(0xffffffffu, m,    off));
            tmin = fminf(tmin, __shfl_xor_sync(0xffffffffu, tmin, off));
        }
        const unsigned Tk = fkey(tmin);

        int cnt = 0;
        for (int base = 0; base < SEQ; base += 32) {
            int i = base + lane;
            unsigned key = fkey(Srow[i]);
            bool kp = key >= Tk;
            unsigned bm = __ballot_sync(0xffffffffu, kp);
            if (kp) {
                int pos = cnt + __popc(bm & lmlt);
                if (pos < CCAP) { chk[pos] = key; chi[pos] = i; }
            }
            cnt += __popc(bm);
        }
        __syncwarp();

        const bool okc = (cnt >= U_TOP && cnt <= CCAP);
        unsigned kth;
        if (okc) {
            unsigned ck[6];
#pragma unroll
            for (int t = 0; t < 6; t++) {
                int p = lane + t * 32;
                ck[t] = (p < cnt) ? chk[p] : 0u;
            }
            unsigned lo = Tk, hi = fkey(m);
            while (lo < hi) {
                unsigned mid = lo + ((hi - lo + 1) >> 1);
                int c = 0;
#pragma unroll
                for (int t = 0; t < 6; t++) c += (ck[t] >= mid) ? 1 : 0;
                c = __reduce_add_sync(0xffffffffu, c);
                if (c >= U_TOP) lo = mid; else hi = mid - 1;
            }
            kth = lo;
        } else {
            kth = radix_select(Srow, myhist, lane);
        }

        float lsum = 0.f;
        int nk = 0;
        if (okc) {
            for (int base = 0; base < cnt; base += 32) {
                int p = base + lane;
                unsigned key = (p < cnt) ? chk[p] : 0u;
                int idx      = (p < cnt) ? chi[p] : 0;
                __syncwarp();
                bool kp = (p < cnt) && (key >= kth);
                unsigned bm = __ballot_sync(0xffffffffu, kp);
                if (kp) {
                    float w = __expf(unfkey(key) - m);
                    lsum += w;
                    int pos = nk + __popc(bm & lmlt);
                    chi[pos] = idx;
                    chk[pos] = __float_as_uint(w);
                }
                nk += __popc(bm);
            }
        } else {
            for (int base = 0; base < SEQ; base += 32) {
                int i = base + lane;
                float s = Srow[i];
                bool kp = fkey(s) >= kth;
                unsigned bm = __ballot_sync(0xffffffffu, kp);
                if (kp) {
                    float w = __expf(s - m);
                    lsum += w;
                    int pos = nk + __popc(bm & lmlt);
                    if (pos < CCAP) { chi[pos] = i; chk[pos] = __float_as_uint(w); }
                }
                nk += __popc(bm);
            }
        }
        __syncwarp();
#pragma unroll
        for (int off = 16; off; off >>= 1)
            lsum += __shfl_xor_sync(0xffffffffu, lsum, off);
        const float scale = 1.f / lsum;

        float c0 = 0.f, c1 = 0.f;
        if (nk <= CCAP) {
            for (int j = 0; j < nk; j++) {
                int kkidx = chi[j];
                float w = __uint_as_float(chk[j]);
                const float* vr = Vbase + (size_t)kkidx * DMODEL;
                c0 += w * vr[lane];
                c1 += w * vr[lane + 32];
            }
        } else {
            for (int i = 0; i < SEQ; i++) {
                float s = Srow[i];
                if (fkey(s) >= kth) {
                    float w = __expf(s - m);
                    const float* vr = Vbase + (size_t)i * DMODEL;
                    c0 += w * vr[lane];
                    c1 += w * vr[lane + 32];
                }
            }
        }
        float* orow = ctx + ((size_t)b * SEQ + q0 + q) * DMODEL + h * HDIM;
        orow[lane]      = c0 * scale;
        orow[lane + 32] = c1 * scale;
    }
}

// ---------------- launch ----------------------------------------------------
extern "C" void kernel_launch(void* const* d_in, const int* in_sizes, int n_in,
                              void* d_out, int out_size)
{
    const float* x  = (const float*)d_in[0];
    const float* Wq = (const float*)d_in[1];
    const float* bq = (const float*)d_in[2];
    const float* Wk = (const float*)d_in[3];
    const float* bk = (const float*)d_in[4];
    const float* Wv = (const float*)d_in[5];
    const float* bv = (const float*)d_in[6];
    const float* Wo = (const float*)d_in[7];
    const float* bo = (const float*)d_in[8];
    float* out = (float*)d_out;

    float *Q, *K, *V, *C;
    cudaGetSymbolAddress((void**)&Q, g_Q);
    cudaGetSymbolAddress((void**)&K, g_Kp);
    cudaGetSymbolAddress((void**)&V, g_Vp);
    cudaGetSymbolAddress((void**)&C, g_ctx);
    __nv_bfloat16 *xh,*xl,*ch,*cl,*wvh,*wvl,*woh,*wol;
    cudaGetSymbolAddress((void**)&xh, g_xh);   cudaGetSymbolAddress((void**)&xl, g_xl);
    cudaGetSymbolAddress((void**)&ch, g_ch);   cudaGetSymbolAddress((void**)&cl, g_cl);
    cudaGetSymbolAddress((void**)&wvh, g_wvh); cudaGetSymbolAddress((void**)&wvl, g_wvl);
    cudaGetSymbolAddress((void**)&woh, g_woh); cudaGetSymbolAddress((void**)&wol, g_wol);

    // Q,K: exact fp32 FFMA2 pipelined path (selection-critical)
    qk_gemm<<<dim3(DMODEL / GBN, ROWS / GBM, 2), 256>>>(x, Wq, bq, Q, Wk, bk, K);

    // V: HMMA bf16x3 (precision-insensitive, measured fast)
    cvt_split<<<1024, 256>>>(x,  xh,  xl,  ROWS*DMODEL/4);
    cvt_split<<<512, 256>>>(Wv, wvh, wvl, DMODEL*DMODEL/4);
    cvt_split<<<512, 256>>>(Wo, woh, wol, DMODEL*DMODEL/4);
    tc_gemm1<<<dim3(DMODEL/128, ROWS/128), 256>>>(xh, xl, wvh, wvl, bv, V);

    cudaFuncSetAttribute(attn_kernel, cudaFuncAttributeMaxDynamicSharedMemorySize,
                         ATTN_SMEM_BYTES);
    attn_kernel<<<dim3(SEQ / TQ, BH), ATHREADS, ATTN_SMEM_BYTES>>>(Q, K, V, C);

    cvt_split<<<1024, 256>>>(C, ch, cl, ROWS*DMODEL/4);
    tc_gemm1<<<dim3(DMODEL/128, ROWS/128), 256>>>(ch, cl, woh, wol, bo, out);
}

// round 14
// speedup vs baseline: 1.2812x; 1.1447x over previous
#include <cuda_runtime.h>
#include <cuda_bf16.h>
#include <math.h>

#define BATCH   2
#define SEQ     2048
#define DMODEL  1024
#define NHEAD   16
#define HDIM    64
#define BH      (BATCH*NHEAD)      // 32
#define ROWS    (BATCH*SEQ)        // 4096
#define U_TOP   38                 // int(5 * ln(2048)) = 38
#define CCAP    320                // candidate buffer per row (u16 indices)
#define WBU     480                // u32 words per warp: 320 keys + 320 u16 idx

typedef unsigned long long ull;

// ---- packed f32x2 helpers ---------------------------------------------------
__device__ __forceinline__ ull pk2(float x, float y) {
    ull r; asm("mov.b64 %0, {%1, %2};" : "=l"(r) : "f"(x), "f"(y)); return r;
}
__device__ __forceinline__ void ffma2(ull& d, ull a, ull b) {
    asm("fma.rn.f32x2 %0, %1, %2, %0;" : "+l"(d) : "l"(a), "l"(b));
}
__device__ __forceinline__ float2 up2(ull v) {
    float2 f; asm("mov.b64 {%0, %1}, %2;" : "=f"(f.x), "=f"(f.y) : "l"(v)); return f;
}
union f4u { float4 f; ull u[2]; };

// ---------------- scratch ----------------------------------------------------
__device__ __align__(256) float g_Q[ROWS * DMODEL];
__device__ __align__(256) float g_Kp[ROWS * DMODEL];
__device__ __align__(256) float g_Vp[ROWS * DMODEL];
__device__ __align__(256) float g_ctx[ROWS * DMODEL];
__device__ __align__(256) __nv_bfloat16 g_xh[ROWS * DMODEL],  g_xl[ROWS * DMODEL];
__device__ __align__(256) __nv_bfloat16 g_ch[ROWS * DMODEL],  g_cl[ROWS * DMODEL];
__device__ __align__(256) __nv_bfloat16 g_wvh[DMODEL*DMODEL], g_wvl[DMODEL*DMODEL];
__device__ __align__(256) __nv_bfloat16 g_woh[DMODEL*DMODEL], g_wol[DMODEL*DMODEL];

// =================== FFMA2 SGEMM, 16m x 8n, register-staged (R11, measured) ==
#define GBM 256
#define GBN 128
#define GBK 16
#define NKC (DMODEL / GBK)

__device__ __forceinline__
void gemm_body(const float* __restrict__ A, const float* __restrict__ Bw,
               const float* __restrict__ bias, float* __restrict__ C,
               int m0, int n0, int N)
{
    __shared__ float As[GBK][GBM];
    __shared__ float Bs[GBK][GBN];

    const int tid = threadIdx.x;
    const int tx = tid & 15;
    const int ty = tid >> 4;

    const int arow0 = tid >> 2,  akq = tid & 3;
    const int brow0 = tid >> 2,  bkq = tid & 3;

    ull acc2[8][8];
#pragma unroll
    for (int i = 0; i < 8; i++)
#pragma unroll
        for (int j = 0; j < 8; j++) acc2[i][j] = 0ull;

    float4 pa[4], pb[2];
#pragma unroll
    for (int i = 0; i < 4; i++)
        pa[i] = *(const float4*)(A + (size_t)(m0 + arow0 + i * 64) * DMODEL + akq * 4);
#pragma unroll
    for (int i = 0; i < 2; i++)
        pb[i] = *(const float4*)(Bw + (size_t)(n0 + brow0 + i * 64) * DMODEL + bkq * 4);

    for (int c = 0; c < NKC; c++) {
        __syncthreads();
#pragma unroll
        for (int i = 0; i < 4; i++) {
            int row = arow0 + i * 64;
            As[akq*4+0][row] = pa[i].x; As[akq*4+1][row] = pa[i].y;
            As[akq*4+2][row] = pa[i].z; As[akq*4+3][row] = pa[i].w;
        }
#pragma unroll
        for (int i = 0; i < 2; i++) {
            int row = brow0 + i * 64;
            Bs[bkq*4+0][row] = pb[i].x; Bs[bkq*4+1][row] = pb[i].y;
            Bs[bkq*4+2][row] = pb[i].z; Bs[bkq*4+3][row] = pb[i].w;
        }
        if (c + 1 < NKC) {
            const int k0 = (c + 1) * GBK;
#pragma unroll
            for (int i = 0; i < 4; i++)
                pa[i] = *(const float4*)(A + (size_t)(m0 + arow0 + i * 64) * DMODEL + k0 + akq * 4);
#pragma unroll
            for (int i = 0; i < 2; i++)
                pb[i] = *(const float4*)(Bw + (size_t)(n0 + brow0 + i * 64) * DMODEL + k0 + bkq * 4);
        }
        __syncthreads();

#pragma unroll
        for (int kk = 0; kk < GBK; kk++) {
            f4u a4[4];
#pragma unroll
            for (int q = 0; q < 4; q++)
                a4[q].f = *(float4*)&As[kk][ty * 16 + q * 4];
            float bf[8];
            *(float4*)&bf[0] = *(float4*)&Bs[kk][tx * 8];
            *(float4*)&bf[4] = *(float4*)&Bs[kk][tx * 8 + 4];
            ull bd[8];
#pragma unroll
            for (int j = 0; j < 8; j++) bd[j] = pk2(bf[j], bf[j]);
#pragma unroll
            for (int mp = 0; mp < 8; mp++) {
                ull ap = a4[mp >> 1].u[mp & 1];
#pragma unroll
                for (int j = 0; j < 8; j++) ffma2(acc2[mp][j], ap, bd[j]);
            }
        }
    }

    float bc[8];
#pragma unroll
    for (int j = 0; j < 8; j++) bc[j] = bias[n0 + tx * 8 + j];

#pragma unroll
    for (int mp = 0; mp < 8; mp++) {
        const int rowe = m0 + ty * 16 + mp * 2;
        float2 p[8];
#pragma unroll
        for (int j = 0; j < 8; j++) p[j] = up2(acc2[mp][j]);
        float4 e0 = make_float4(p[0].x + bc[0], p[1].x + bc[1], p[2].x + bc[2], p[3].x + bc[3]);
        float4 e1 = make_float4(p[4].x + bc[4], p[5].x + bc[5], p[6].x + bc[6], p[7].x + bc[7]);
        float4 o0 = make_float4(p[0].y + bc[0], p[1].y + bc[1], p[2].y + bc[2], p[3].y + bc[3]);
        float4 o1 = make_float4(p[4].y + bc[4], p[5].y + bc[5], p[6].y + bc[6], p[7].y + bc[7]);
        float* r0 = C + (size_t)rowe * N + n0 + tx * 8;
        float* r1 = C + (size_t)(rowe + 1) * N + n0 + tx * 8;
        *(float4*)(r0)     = e0;  *(float4*)(r0 + 4) = e1;
        *(float4*)(r1)     = o0;  *(float4*)(r1 + 4) = o1;
    }
}

__global__ __launch_bounds__(256)
void qk_gemm(const float* __restrict__ x,
             const float* __restrict__ Wq, const float* __restrict__ bq, float* __restrict__ Q,
             const float* __restrict__ Wk, const float* __restrict__ bk, float* __restrict__ K)
{
    const int sel = blockIdx.z;
    const float* W = (sel == 0) ? Wq : Wk;
    const float* b = (sel == 0) ? bq : bk;
    float*       C = (sel == 0) ? Q  : K;
    gemm_body(x, W, b, C, blockIdx.y * GBM, blockIdx.x * GBN, DMODEL);
}

// =================== HMMA helpers (V / out-proj: measured ~87us each) ========
__device__ __forceinline__ unsigned smem_u32(const void* p) {
    unsigned a;
    asm("{ .reg .u64 t; cvta.to.shared.u64 t, %1; cvt.u32.u64 %0, t; }"
        : "=r"(a) : "l"(p));
    return a;
}
__device__ __forceinline__ void ldsm_x4(unsigned* r, unsigned addr) {
    asm volatile("ldmatrix.sync.aligned.m8n8.x4.shared.b16 {%0,%1,%2,%3}, [%4];"
                 : "=r"(r[0]), "=r"(r[1]), "=r"(r[2]), "=r"(r[3]) : "r"(addr));
}
__device__ __forceinline__ void mma16816(float* c, const unsigned* a, const unsigned* b) {
    asm volatile("mma.sync.aligned.m16n8k16.row.col.f32.bf16.bf16.f32 "
                 "{%0,%1,%2,%3}, {%4,%5,%6,%7}, {%8,%9}, {%0,%1,%2,%3};"
                 : "+f"(c[0]), "+f"(c[1]), "+f"(c[2]), "+f"(c[3])
                 : "r"(a[0]), "r"(a[1]), "r"(a[2]), "r"(a[3]), "r"(b[0]), "r"(b[1]));
}
__device__ __forceinline__ void cp_async16(unsigned dst, const void* src) {
    asm volatile("cp.async.cg.shared.global [%0], [%1], 16;" :: "r"(dst), "l"(src));
}
#define CP_COMMIT() asm volatile("cp.async.commit_group;" ::: "memory")

__global__ __launch_bounds__(256)
void cvt_split(const float* __restrict__ src, __nv_bfloat16* __restrict__ hi,
               __nv_bfloat16* __restrict__ lo, int n4)
{
    int i = blockIdx.x * blockDim.x + threadIdx.x;
    for (; i < n4; i += gridDim.x * blockDim.x) {
        float4 v = *((const float4*)src + i);
        __nv_bfloat16 h0 = __float2bfloat16(v.x), h1 = __float2bfloat16(v.y);
        __nv_bfloat16 h2 = __float2bfloat16(v.z), h3 = __float2bfloat16(v.w);
        __nv_bfloat16 l0 = __float2bfloat16(v.x - __bfloat162float(h0));
        __nv_bfloat16 l1 = __float2bfloat16(v.y - __bfloat162float(h1));
        __nv_bfloat16 l2 = __float2bfloat16(v.z - __bfloat162float(h2));
        __nv_bfloat16 l3 = __float2bfloat16(v.w - __bfloat162float(h3));
        __nv_bfloat162 hh[2] = { {h0, h1}, {h2, h3} };
        __nv_bfloat162 ll[2] = { {l0, l1}, {l2, l3} };
        *((float2*)hi + i) = *(float2*)hh;
        *((float2*)lo + i) = *(float2*)ll;
    }
}

#define NCHUNK (DMODEL / 16)
#define ROWB   48
#define TILEB  (128 * ROWB)
#define STAGEB (4 * TILEB)

__device__ __forceinline__
void tc_gemm_body(const __nv_bfloat16* __restrict__ Ah, const __nv_bfloat16* __restrict__ Al,
                  const __nv_bfloat16* __restrict__ Bh, const __nv_bfloat16* __restrict__ Bl,
                  const float* __restrict__ bias, float* __restrict__ C,
                  int m0, int n0, int ldc)
{
    __shared__ __align__(16) char stage[2 * STAGEB];
    const unsigned sbase = smem_u32(stage);

    const int tid  = threadIdx.x;
    const int lane = tid & 31;
    const int wid  = tid >> 5;
    const int wm   = wid & 3;
    const int wn   = wid >> 2;

    const int lrow  = tid >> 1;
    const int lhalf = tid & 1;
    const __nv_bfloat16* gsrc[4] = {
        Ah + (size_t)(m0 + lrow) * DMODEL + lhalf * 8,
        Al + (size_t)(m0 + lrow) * DMODEL + lhalf * 8,
        Bh + (size_t)(n0 + lrow) * DMODEL + lhalf * 8,
        Bl + (size_t)(n0 + lrow) * DMODEL + lhalf * 8 };
    const unsigned sdst = sbase + lrow * ROWB + lhalf * 16;

    float acc[2][8][4];
#pragma unroll
    for (int i = 0; i < 2; i++)
#pragma unroll
        for (int j = 0; j < 8; j++)
#pragma unroll
            for (int k = 0; k < 4; k++) acc[i][j][k] = 0.f;

#pragma unroll
    for (int t = 0; t < 4; t++)
        cp_async16(sdst + t * TILEB, gsrc[t]);
    CP_COMMIT();

    const int arow = wm * 32 + (lane & 15);
    const unsigned a_off = arow * ROWB + (lane >> 4) * 16;
    const int brow = wn * 64 + ((lane >> 4) << 3) + (lane & 7);
    const unsigned b_off = brow * ROWB + ((lane >> 3) & 1) * 16;

    for (int c = 0; c < NCHUNK; c++) {
        if (c + 1 < NCHUNK) {
            const unsigned sd = sdst + ((c + 1) & 1) * STAGEB;
#pragma unroll
            for (int t = 0; t < 4; t++)
                cp_async16(sd + t * TILEB, gsrc[t] + (size_t)(c + 1) * 16);
            CP_COMMIT();
            asm volatile("cp.async.wait_group 1;" ::: "memory");
        } else {
            asm volatile("cp.async.wait_group 0;" ::: "memory");
        }
        __syncthreads();

        const unsigned sb = sbase + (c & 1) * STAGEB;
        unsigned ah[2][4], al[2][4];
#pragma unroll
        for (int mt = 0; mt < 2; mt++) {
            ldsm_x4(ah[mt], sb + 0 * TILEB + a_off + mt * 16 * ROWB);
            ldsm_x4(al[mt], sb + 1 * TILEB + a_off + mt * 16 * ROWB);
        }
#pragma unroll
        for (int p = 0; p < 4; p++) {
            unsigned bh4[4], bl4[4];
            ldsm_x4(bh4, sb + 2 * TILEB + b_off + p * 16 * ROWB);
            ldsm_x4(bl4, sb + 3 * TILEB + b_off + p * 16 * ROWB);
#pragma unroll
            for (int mt = 0; mt < 2; mt++) {
                mma16816(acc[mt][2*p+0], ah[mt], bh4 + 0);
                mma16816(acc[mt][2*p+0], ah[mt], bl4 + 0);
                mma16816(acc[mt][2*p+0], al[mt], bh4 + 0);
                mma16816(acc[mt][2*p+1], ah[mt], bh4 + 2);
                mma16816(acc[mt][2*p+1], ah[mt], bl4 + 2);
                mma16816(acc[mt][2*p+1], al[mt], bh4 + 2);
            }
        }
        __syncthreads();
    }

    const int g = lane >> 2, qd = lane & 3;
#pragma unroll
    for (int mt = 0; mt < 2; mt++) {
        const int rowg = m0 + wm * 32 + mt * 16 + g;
#pragma unroll
        for (int nt = 0; nt < 8; nt++) {
            const int colg = n0 + wn * 64 + nt * 8 + qd * 2;
            const float b0 = bias[colg], b1 = bias[colg + 1];
            float2 o0 = make_float2(acc[mt][nt][0] + b0, acc[mt][nt][1] + b1);
            float2 o1 = make_float2(acc[mt][nt][2] + b0, acc[mt][nt][3] + b1);
            *(float2*)(C + (size_t)rowg * ldc + colg)       = o0;
            *(float2*)(C + (size_t)(rowg + 8) * ldc + colg) = o1;
        }
    }
}

__global__ __launch_bounds__(256)
void tc_gemm1(const __nv_bfloat16* __restrict__ a0, const __nv_bfloat16* __restrict__ a1,
              const __nv_bfloat16* __restrict__ w0, const __nv_bfloat16* __restrict__ w1,
              const float* __restrict__ b, float* __restrict__ C)
{
    tc_gemm_body(a0, a1, w0, w1, b, C, blockIdx.y * 128, blockIdx.x * 128, DMODEL);
}

// ---------------- fused ProbSparse attention (R8 + CCAP=320/u16 idx) --------
#define TQ 16
#define KT 512
#define ATHREADS 512
#define NCC (SEQ / KT * 2)          // 8 chunk-iterations

__device__ __forceinline__ unsigned fkey(float x) {
    unsigned u = __float_as_uint(x);
    return (u & 0x80000000u) ? ~u : (u | 0x80000000u);
}
__device__ __forceinline__ float unfkey(unsigned k) {
    unsigned u = (k & 0x80000000u) ? (k ^ 0x80000000u) : ~k;
    return __uint_as_float(u);
}

__device__ unsigned radix_select(const float* __restrict__ Srow,
                                 unsigned* __restrict__ myhist, int lane)
{
    unsigned prefix = 0;
    int remaining = U_TOP;
    for (int pass = 0; pass < 4; pass++) {
        const int shift = 24 - pass * 8;
#pragma unroll
        for (int j = 0; j < 8; j++) myhist[lane * 8 + j] = 0;
        __syncwarp();
        for (int i = lane; i < SEQ; i += 32) {
            unsigned key = fkey(Srow[i]);
            bool ok = (pass == 0) || ((key >> (shift + 8)) == prefix);
            if (ok) atomicAdd(&myhist[(key >> shift) & 255], 1u);
        }
        __syncwarp();
        unsigned psum = 0;
#pragma unroll
        for (int j = 0; j < 8; j++) psum += myhist[lane * 8 + j];
        unsigned c = psum;
#pragma unroll
        for (int off = 1; off < 32; off <<= 1) {
            unsigned o = __shfl_down_sync(0xffffffffu, c, off);
            if (lane + off < 32) c += o;
        }
        unsigned mk = __ballot_sync(0xffffffffu, c >= (unsigned)remaining);
        int lsel = 31 - __clz(mk);
        int digit = 0, newrem = remaining;
        if (lane == lsel) {
            unsigned cum = c - psum;
            for (int j = 7; j >= 0; j--) {
                unsigned hv = myhist[lsel * 8 + j];
                cum += hv;
                if (cum >= (unsigned)remaining) {
                    digit = lsel * 8 + j;
                    newrem = remaining - (int)(cum - hv);
                    break;
                }
            }
        }
        digit  = __shfl_sync(0xffffffffu, digit, lsel);
        newrem = __shfl_sync(0xffffffffu, newrem, lsel);
        prefix = (prefix << 8) | (unsigned)digit;
        remaining = newrem;
        __syncwarp();
    }
    return prefix;
}

// smem: S[16*2048] | Qs[16*64] | Ks[512*32 swizzled] | wbuf[16 warps * 480 u32]
#define ATTN_SMEM_BYTES ((TQ*SEQ + TQ*64 + KT*32) * 4 + 16*WBU*4)

__global__ __launch_bounds__(ATHREADS)
void attn_kernel(const float* __restrict__ Q, const float* __restrict__ K,
                 const float* __restrict__ V, float* __restrict__ ctx)
{
    extern __shared__ char smraw[];
    float*    S    = (float*)smraw;
    float*    Qs   = S  + TQ * SEQ;
    float*    Ks   = Qs + TQ * 64;                 // 512 rows x 32 floats, swizzled
    unsigned* wbuf = (unsigned*)(Ks + KT * 32);    // 16 * WBU

    const int tid = threadIdx.x;
    const int qt  = blockIdx.x;
    const int bh  = blockIdx.y;
    const int b   = bh >> 4, h = bh & 15;
    const int q0  = qt * TQ;

    const float* Qbase = Q + ((size_t)b * SEQ + q0) * DMODEL + h * HDIM;
    const float* Kbase = K + ((size_t)b * SEQ) * DMODEL + h * HDIM;
    const float* Vbase = V + ((size_t)b * SEQ) * DMODEL + h * HDIM;

    if (tid < 256) {
        int row = tid >> 4, c4 = tid & 15;
        *(float4*)(Qs + row * 64 + c4 * 4) =
            *(const float4*)(Qbase + (size_t)row * DMODEL + c4 * 4);
    }

    // ---- phase 1: scores, 4q x 4k per thread (R8 verbatim) ----
    const int kq  = tid & 127;
    const int qg  = tid >> 7;
    const int swz = kq & 7;

    const int prow = tid >> 3;
    const int pd4  = tid & 7;

    float4 st[8];
#pragma unroll
    for (int i = 0; i < 8; i++) {
        int row = i * 64 + prow;
        st[i] = *(const float4*)(Kbase + (size_t)row * DMODEL + pd4 * 4);
    }

    ull acc2[4][4];

    for (int cc = 0; cc < NCC; cc++) {
        const int ch = cc & 1;
        const int kb = (cc >> 1) * KT;

        __syncthreads();
#pragma unroll
        for (int i = 0; i < 8; i++) {
            int row = i * 64 + prow;
            *(float4*)(Ks + row * 32 + ((pd4 ^ ((row >> 2) & 7)) << 2)) = st[i];
        }
        if (cc + 1 < NCC) {
            const int nch = (cc + 1) & 1;
            const int nkb = ((cc + 1) >> 1) * KT;
#pragma unroll
            for (int i = 0; i < 8; i++) {
                int row = i * 64 + prow;
                st[i] = *(const float4*)(Kbase + (size_t)(nkb + row) * DMODEL
                                         + nch * 32 + pd4 * 4);
            }
        }
        __syncthreads();

        if (ch == 0) {
#pragma unroll
            for (int j = 0; j < 4; j++)
#pragma unroll
                for (int i = 0; i < 4; i++) acc2[j][i] = 0ull;
        }

#pragma unroll
        for (int d4 = 0; d4 < 8; d4++) {
            f4u kv[4];
#pragma unroll
            for (int i = 0; i < 4; i++)
                kv[i].f = *(float4*)(Ks + (kq * 4 + i) * 32 + ((d4 ^ swz) << 2));
#pragma unroll
            for (int j = 0; j < 4; j++) {
                f4u qv;
                qv.f = *(float4*)(Qs + (qg * 4 + j) * 64 + ch * 32 + (d4 << 2));
#pragma unroll
                for (int i = 0; i < 4; i++) {
                    ffma2(acc2[j][i], qv.u[0], kv[i].u[0]);
                    ffma2(acc2[j][i], qv.u[1], kv[i].u[1]);
                }
            }
        }

        if (ch == 1) {
#pragma unroll
            for (int j = 0; j < 4; j++) {
                float2 r0 = up2(acc2[j][0]), r1 = up2(acc2[j][1]);
                float2 r2 = up2(acc2[j][2]), r3 = up2(acc2[j][3]);
                float4 o = make_float4((r0.x + r0.y) * 0.125f, (r1.x + r1.y) * 0.125f,
                                       (r2.x + r2.y) * 0.125f, (r3.x + r3.y) * 0.125f);
                *(float4*)(S + (size_t)(qg * 4 + j) * SEQ + kb + kq * 4) = o;
            }
        }
    }
    __syncthreads();

    // ---- phase 2: 1 row per warp, CCAP=320 with u16 indices ----
    const int lane = tid & 31, wid = tid >> 5;
    const unsigned lmlt = (1u << lane) - 1u;
    unsigned*       chk = wbuf + wid * WBU;             // 320 keys/weights (u32)
    unsigned short* chi = (unsigned short*)(chk + CCAP); // 320 indices (u16)
    unsigned*       myhist = chk;                        // radix fallback alias

    {
        const int q = wid;
        const float* Srow = S + (size_t)q * SEQ;

        float lm = -1e30f;
        for (int i = lane; i < SEQ; i += 32) lm = fmaxf(lm, Srow[i]);
        float m = lm, tmin = lm;
#pragma unroll
        for (int off = 16; off; off >>= 1) {
            m    = fmaxf(m,    __shfl_xor_sync(0xffffffffu, m,    off));
            tmin = fminf(tmin, __shfl_xor_sync(0xffffffffu, tmin, off));
        }
        const unsigned Tk = fkey(tmin);

        int cnt = 0;
        for (int base = 0; base < SEQ; base += 32) {
            int i = base + lane;
            unsigned key = fkey(Srow[i]);
            bool kp = key >= Tk;
            unsigned bm = __ballot_sync(0xffffffffu, kp);
            if (kp) {
                int pos = cnt + __popc(bm & lmlt);
                if (pos < CCAP) { chk[pos] = key; chi[pos] = (unsigned short)i; }
            }
            cnt += __popc(bm);
        }
        __syncwarp();

        const bool okc = (cnt >= U_TOP && cnt <= CCAP);
        unsigned kth;
        if (okc) {
            unsigned ck[10];
#pragma unroll
            for (int t = 0; t < 10; t++) {
                int p = lane + t * 32;
                ck[t] = (p < cnt) ? chk[p] : 0u;
            }
            unsigned lo = Tk, hi = fkey(m);
            while (lo < hi) {
                unsigned mid = lo + ((hi - lo + 1) >> 1);
                int c = 0;
#pragma unroll
                for (int t = 0; t < 10; t++) c += (ck[t] >= mid) ? 1 : 0;
                c = __reduce_add_sync(0xffffffffu, c);
                if (c >= U_TOP) lo = mid; else hi = mid - 1;
            }
            kth = lo;
        } else {
            kth = radix_select(Srow, myhist, lane);
        }

        float lsum = 0.f;
        int nk = 0;
        if (okc) {
            for (int base = 0; base < cnt; base += 32) {
                int p = base + lane;
                unsigned key = (p < cnt) ? chk[p] : 0u;
                int idx      = (p < cnt) ? (int)chi[p] : 0;
                __syncwarp();
                bool kp = (p < cnt) && (key >= kth);
                unsigned bm = __ballot_sync(0xffffffffu, kp);
                if (kp) {
                    float w = __expf(unfkey(key) - m);
                    lsum += w;
                    int pos = nk + __popc(bm & lmlt);
                    chi[pos] = (unsigned short)idx;
                    chk[pos] = __float_as_uint(w);
                }
                nk += __popc(bm);
            }
        } else {
            for (int base = 0; base < SEQ; base += 32) {
                int i = base + lane;
                float s = Srow[i];
                bool kp = fkey(s) >= kth;
                unsigned bm = __ballot_sync(0xffffffffu, kp);
                if (kp) {
                    float w = __expf(s - m);
                    lsum += w;
                    int pos = nk + __popc(bm & lmlt);
                    if (pos < CCAP) { chi[pos] = (unsigned short)i; chk[pos] = __float_as_uint(w); }
                }
                nk += __popc(bm);
            }
        }
        __syncwarp();
#pragma unroll
        for (int off = 16; off; off >>= 1)
            lsum += __shfl_xor_sync(0xffffffffu, lsum, off);
        const float scale = 1.f / lsum;

        float c0 = 0.f, c1 = 0.f;
        if (nk <= CCAP) {
            for (int j = 0; j < nk; j++) {
                int kkidx = (int)chi[j];
                float w = __uint_as_float(chk[j]);
                const float* vr = Vbase + (size_t)kkidx * DMODEL;
                c0 += w * vr[lane];
                c1 += w * vr[lane + 32];
            }
        } else {
            for (int i = 0; i < SEQ; i++) {
                float s = Srow[i];
                if (fkey(s) >= kth) {
                    float w = __expf(s - m);
                    const float* vr = Vbase + (size_t)i * DMODEL;
                    c0 += w * vr[lane];
                    c1 += w * vr[lane + 32];
                }
            }
        }
        float* orow = ctx + ((size_t)b * SEQ + q0 + q) * DMODEL + h * HDIM;
        orow[lane]      = c0 * scale;
        orow[lane + 32] = c1 * scale;
    }
}

// ---------------- launch ----------------------------------------------------
extern "C" void kernel_launch(void* const* d_in, const int* in_sizes, int n_in,
                              void* d_out, int out_size)
{
    const float* x  = (const float*)d_in[0];
    const float* Wq = (const float*)d_in[1];
    const float* bq = (const float*)d_in[2];
    const float* Wk = (const float*)d_in[3];
    const float* bk = (const float*)d_in[4];
    const float* Wv = (const float*)d_in[5];
    const float* bv = (const float*)d_in[6];
    const float* Wo = (const float*)d_in[7];
    const float* bo = (const float*)d_in[8];
    float* out = (float*)d_out;

    float *Q, *K, *V, *C;
    cudaGetSymbolAddress((void**)&Q, g_Q);
    cudaGetSymbolAddress((void**)&K, g_Kp);
    cudaGetSymbolAddress((void**)&V, g_Vp);
    cudaGetSymbolAddress((void**)&C, g_ctx);
    __nv_bfloat16 *xh,*xl,*ch,*cl,*wvh,*wvl,*woh,*wol;
    cudaGetSymbolAddress((void**)&xh, g_xh);   cudaGetSymbolAddress((void**)&xl, g_xl);
    cudaGetSymbolAddress((void**)&ch, g_ch);   cudaGetSymbolAddress((void**)&cl, g_cl);
    cudaGetSymbolAddress((void**)&wvh, g_wvh); cudaGetSymbolAddress((void**)&wvl, g_wvl);
    cudaGetSymbolAddress((void**)&woh, g_woh); cudaGetSymbolAddress((void**)&wol, g_wol);

    // Q,K: exact fp32 FFMA2 pipelined path (selection-critical)
    qk_gemm<<<dim3(DMODEL / GBN, ROWS / GBM, 2), 256>>>(x, Wq, bq, Q, Wk, bk, K);

    // V: HMMA bf16x3 (precision-insensitive, measured fast)
    cvt_split<<<1024, 256>>>(x,  xh,  xl,  ROWS*DMODEL/4);
    cvt_split<<<512, 256>>>(Wv, wvh, wvl, DMODEL*DMODEL/4);
    cvt_split<<<512, 256>>>(Wo, woh, wol, DMODEL*DMODEL/4);
    tc_gemm1<<<dim3(DMODEL/128, ROWS/128), 256>>>(xh, xl, wvh, wvl, bv, V);

    cudaFuncSetAttribute(attn_kernel, cudaFuncAttributeMaxDynamicSharedMemorySize,
                         ATTN_SMEM_BYTES);
    attn_kernel<<<dim3(SEQ / TQ, BH), ATHREADS, ATTN_SMEM_BYTES>>>(Q, K, V, C);

    cvt_split<<<1024, 256>>>(C, ch, cl, ROWS*DMODEL/4);
    tc_gemm1<<<dim3(DMODEL/128, ROWS/128), 256>>>(ch, cl, woh, wol, bo, out);
}

// round 16
// speedup vs baseline: 1.3672x; 1.0671x over previous
#include <cuda_runtime.h>
#include <cuda_bf16.h>
#include <math.h>

#define BATCH   2
#define SEQ     2048
#define DMODEL  1024
#define NHEAD   16
#define HDIM    64
#define BH      (BATCH*NHEAD)      // 32
#define ROWS    (BATCH*SEQ)        // 4096
#define SROWS   (BH*SEQ)           // 65536 score rows
#define U_TOP   38                 // int(5 * ln(2048)) = 38
#define CCAP    320                // candidate buffer per row (u16 indices)
#define WBU     480                // u32 words per warp: 320 keys + 320 u16 idx

typedef unsigned long long ull;

// ---- packed f32x2 helpers ---------------------------------------------------
__device__ __forceinline__ ull pk2(float x, float y) {
    ull r; asm("mov.b64 %0, {%1, %2};" : "=l"(r) : "f"(x), "f"(y)); return r;
}
__device__ __forceinline__ void ffma2(ull& d, ull a, ull b) {
    asm("fma.rn.f32x2 %0, %1, %2, %0;" : "+l"(d) : "l"(a), "l"(b));
}
__device__ __forceinline__ float2 up2(ull v) {
    float2 f; asm("mov.b64 {%0, %1}, %2;" : "=f"(f.x), "=f"(f.y) : "l"(v)); return f;
}
union f4u { float4 f; ull u[2]; };

// ---------------- scratch ----------------------------------------------------
__device__ __align__(256) float g_Q[ROWS * DMODEL];
__device__ __align__(256) float g_Kp[ROWS * DMODEL];
__device__ __align__(256) float g_Vp[ROWS * DMODEL];
__device__ __align__(256) float g_ctx[ROWS * DMODEL];
__device__ __align__(256) float g_S[(size_t)SROWS * SEQ];   // 512 MB scores (.bss)
__device__ __align__(256) __nv_bfloat16 g_xh[ROWS * DMODEL],  g_xl[ROWS * DMODEL];
__device__ __align__(256) __nv_bfloat16 g_ch[ROWS * DMODEL],  g_cl[ROWS * DMODEL];
__device__ __align__(256) __nv_bfloat16 g_wvh[DMODEL*DMODEL], g_wvl[DMODEL*DMODEL];
__device__ __align__(256) __nv_bfloat16 g_woh[DMODEL*DMODEL], g_wol[DMODEL*DMODEL];

// =================== FFMA2 SGEMM, 16m x 8n, register-staged (R11, measured) ==
#define GBM 256
#define GBN 128
#define GBK 16
#define NKC (DMODEL / GBK)

__device__ __forceinline__
void gemm_body(const float* __restrict__ A, const float* __restrict__ Bw,
               const float* __restrict__ bias, float* __restrict__ C,
               int m0, int n0, int N)
{
    __shared__ float As[GBK][GBM];
    __shared__ float Bs[GBK][GBN];

    const int tid = threadIdx.x;
    const int tx = tid & 15;
    const int ty = tid >> 4;

    const int arow0 = tid >> 2,  akq = tid & 3;
    const int brow0 = tid >> 2,  bkq = tid & 3;

    ull acc2[8][8];
#pragma unroll
    for (int i = 0; i < 8; i++)
#pragma unroll
        for (int j = 0; j < 8; j++) acc2[i][j] = 0ull;

    float4 pa[4], pb[2];
#pragma unroll
    for (int i = 0; i < 4; i++)
        pa[i] = *(const float4*)(A + (size_t)(m0 + arow0 + i * 64) * DMODEL + akq * 4);
#pragma unroll
    for (int i = 0; i < 2; i++)
        pb[i] = *(const float4*)(Bw + (size_t)(n0 + brow0 + i * 64) * DMODEL + bkq * 4);

    for (int c = 0; c < NKC; c++) {
        __syncthreads();
#pragma unroll
        for (int i = 0; i < 4; i++) {
            int row = arow0 + i * 64;
            As[akq*4+0][row] = pa[i].x; As[akq*4+1][row] = pa[i].y;
            As[akq*4+2][row] = pa[i].z; As[akq*4+3][row] = pa[i].w;
        }
#pragma unroll
        for (int i = 0; i < 2; i++) {
            int row = brow0 + i * 64;
            Bs[bkq*4+0][row] = pb[i].x; Bs[bkq*4+1][row] = pb[i].y;
            Bs[bkq*4+2][row] = pb[i].z; Bs[bkq*4+3][row] = pb[i].w;
        }
        if (c + 1 < NKC) {
            const int k0 = (c + 1) * GBK;
#pragma unroll
            for (int i = 0; i < 4; i++)
                pa[i] = *(const float4*)(A + (size_t)(m0 + arow0 + i * 64) * DMODEL + k0 + akq * 4);
#pragma unroll
            for (int i = 0; i < 2; i++)
                pb[i] = *(const float4*)(Bw + (size_t)(n0 + brow0 + i * 64) * DMODEL + k0 + bkq * 4);
        }
        __syncthreads();

#pragma unroll
        for (int kk = 0; kk < GBK; kk++) {
            f4u a4[4];
#pragma unroll
            for (int q = 0; q < 4; q++)
                a4[q].f = *(float4*)&As[kk][ty * 16 + q * 4];
            float bf[8];
            *(float4*)&bf[0] = *(float4*)&Bs[kk][tx * 8];
            *(float4*)&bf[4] = *(float4*)&Bs[kk][tx * 8 + 4];
            ull bd[8];
#pragma unroll
            for (int j = 0; j < 8; j++) bd[j] = pk2(bf[j], bf[j]);
#pragma unroll
            for (int mp = 0; mp < 8; mp++) {
                ull ap = a4[mp >> 1].u[mp & 1];
#pragma unroll
                for (int j = 0; j < 8; j++) ffma2(acc2[mp][j], ap, bd[j]);
            }
        }
    }

    float bc[8];
#pragma unroll
    for (int j = 0; j < 8; j++) bc[j] = bias[n0 + tx * 8 + j];

#pragma unroll
    for (int mp = 0; mp < 8; mp++) {
        const int rowe = m0 + ty * 16 + mp * 2;
        float2 p[8];
#pragma unroll
        for (int j = 0; j < 8; j++) p[j] = up2(acc2[mp][j]);
        float4 e0 = make_float4(p[0].x + bc[0], p[1].x + bc[1], p[2].x + bc[2], p[3].x + bc[3]);
        float4 e1 = make_float4(p[4].x + bc[4], p[5].x + bc[5], p[6].x + bc[6], p[7].x + bc[7]);
        float4 o0 = make_float4(p[0].y + bc[0], p[1].y + bc[1], p[2].y + bc[2], p[3].y + bc[3]);
        float4 o1 = make_float4(p[4].y + bc[4], p[5].y + bc[5], p[6].y + bc[6], p[7].y + bc[7]);
        float* r0 = C + (size_t)rowe * N + n0 + tx * 8;
        float* r1 = C + (size_t)(rowe + 1) * N + n0 + tx * 8;
        *(float4*)(r0)     = e0;  *(float4*)(r0 + 4) = e1;
        *(float4*)(r1)     = o0;  *(float4*)(r1 + 4) = o1;
    }
}

__global__ __launch_bounds__(256)
void qk_gemm(const float* __restrict__ x,
             const float* __restrict__ Wq, const float* __restrict__ bq, float* __restrict__ Q,
             const float* __restrict__ Wk, const float* __restrict__ bk, float* __restrict__ K)
{
    const int sel = blockIdx.z;
    const float* W = (sel == 0) ? Wq : Wk;
    const float* b = (sel == 0) ? bq : bk;
    float*       C = (sel == 0) ? Q  : K;
    gemm_body(x, W, b, C, blockIdx.y * GBM, blockIdx.x * GBN, DMODEL);
}

// =================== HMMA helpers (V / out-proj: measured ~87us each) ========
__device__ __forceinline__ unsigned smem_u32(const void* p) {
    unsigned a;
    asm("{ .reg .u64 t; cvta.to.shared.u64 t, %1; cvt.u32.u64 %0, t; }"
        : "=r"(a) : "l"(p));
    return a;
}
__device__ __forceinline__ void ldsm_x4(unsigned* r, unsigned addr) {
    asm volatile("ldmatrix.sync.aligned.m8n8.x4.shared.b16 {%0,%1,%2,%3}, [%4];"
                 : "=r"(r[0]), "=r"(r[1]), "=r"(r[2]), "=r"(r[3]) : "r"(addr));
}
__device__ __forceinline__ void mma16816(float* c, const unsigned* a, const unsigned* b) {
    asm volatile("mma.sync.aligned.m16n8k16.row.col.f32.bf16.bf16.f32 "
                 "{%0,%1,%2,%3}, {%4,%5,%6,%7}, {%8,%9}, {%0,%1,%2,%3};"
                 : "+f"(c[0]), "+f"(c[1]), "+f"(c[2]), "+f"(c[3])
                 : "r"(a[0]), "r"(a[1]), "r"(a[2]), "r"(a[3]), "r"(b[0]), "r"(b[1]));
}
__device__ __forceinline__ void cp_async16(unsigned dst, const void* src) {
    asm volatile("cp.async.cg.shared.global [%0], [%1], 16;" :: "r"(dst), "l"(src));
}
#define CP_COMMIT() asm volatile("cp.async.commit_group;" ::: "memory")

__global__ __launch_bounds__(256)
void cvt_split(const float* __restrict__ src, __nv_bfloat16* __restrict__ hi,
               __nv_bfloat16* __restrict__ lo, int n4)
{
    int i = blockIdx.x * blockDim.x + threadIdx.x;
    for (; i < n4; i += gridDim.x * blockDim.x) {
        float4 v = *((const float4*)src + i);
        __nv_bfloat16 h0 = __float2bfloat16(v.x), h1 = __float2bfloat16(v.y);
        __nv_bfloat16 h2 = __float2bfloat16(v.z), h3 = __float2bfloat16(v.w);
        __nv_bfloat16 l0 = __float2bfloat16(v.x - __bfloat162float(h0));
        __nv_bfloat16 l1 = __float2bfloat16(v.y - __bfloat162float(h1));
        __nv_bfloat16 l2 = __float2bfloat16(v.z - __bfloat162float(h2));
        __nv_bfloat16 l3 = __float2bfloat16(v.w - __bfloat162float(h3));
        __nv_bfloat162 hh[2] = { {h0, h1}, {h2, h3} };
        __nv_bfloat162 ll[2] = { {l0, l1}, {l2, l3} };
        *((float2*)hi + i) = *(float2*)hh;
        *((float2*)lo + i) = *(float2*)ll;
    }
}

#define NCHUNK (DMODEL / 16)
#define ROWB   48
#define TILEB  (128 * ROWB)
#define STAGEB (4 * TILEB)

__device__ __forceinline__
void tc_gemm_body(const __nv_bfloat16* __restrict__ Ah, const __nv_bfloat16* __restrict__ Al,
                  const __nv_bfloat16* __restrict__ Bh, const __nv_bfloat16* __restrict__ Bl,
                  const float* __restrict__ bias, float* __restrict__ C,
                  int m0, int n0, int ldc)
{
    __shared__ __align__(16) char stage[2 * STAGEB];
    const unsigned sbase = smem_u32(stage);

    const int tid  = threadIdx.x;
    const int lane = tid & 31;
    const int wid  = tid >> 5;
    const int wm   = wid & 3;
    const int wn   = wid >> 2;

    const int lrow  = tid >> 1;
    const int lhalf = tid & 1;
    const __nv_bfloat16* gsrc[4] = {
        Ah + (size_t)(m0 + lrow) * DMODEL + lhalf * 8,
        Al + (size_t)(m0 + lrow) * DMODEL + lhalf * 8,
        Bh + (size_t)(n0 + lrow) * DMODEL + lhalf * 8,
        Bl + (size_t)(n0 + lrow) * DMODEL + lhalf * 8 };
    const unsigned sdst = sbase + lrow * ROWB + lhalf * 16;

    float acc[2][8][4];
#pragma unroll
    for (int i = 0; i < 2; i++)
#pragma unroll
        for (int j = 0; j < 8; j++)
#pragma unroll
            for (int k = 0; k < 4; k++) acc[i][j][k] = 0.f;

#pragma unroll
    for (int t = 0; t < 4; t++)
        cp_async16(sdst + t * TILEB, gsrc[t]);
    CP_COMMIT();

    const int arow = wm * 32 + (lane & 15);
    const unsigned a_off = arow * ROWB + (lane >> 4) * 16;
    const int brow = wn * 64 + ((lane >> 4) << 3) + (lane & 7);
    const unsigned b_off = brow * ROWB + ((lane >> 3) & 1) * 16;

    for (int c = 0; c < NCHUNK; c++) {
        if (c + 1 < NCHUNK) {
            const unsigned sd = sdst + ((c + 1) & 1) * STAGEB;
#pragma unroll
            for (int t = 0; t < 4; t++)
                cp_async16(sd + t * TILEB, gsrc[t] + (size_t)(c + 1) * 16);
            CP_COMMIT();
            asm volatile("cp.async.wait_group 1;" ::: "memory");
        } else {
            asm volatile("cp.async.wait_group 0;" ::: "memory");
        }
        __syncthreads();

        const unsigned sb = sbase + (c & 1) * STAGEB;
        unsigned ah[2][4], al[2][4];
#pragma unroll
        for (int mt = 0; mt < 2; mt++) {
            ldsm_x4(ah[mt], sb + 0 * TILEB + a_off + mt * 16 * ROWB);
            ldsm_x4(al[mt], sb + 1 * TILEB + a_off + mt * 16 * ROWB);
        }
#pragma unroll
        for (int p = 0; p < 4; p++) {
            unsigned bh4[4], bl4[4];
            ldsm_x4(bh4, sb + 2 * TILEB + b_off + p * 16 * ROWB);
            ldsm_x4(bl4, sb + 3 * TILEB + b_off + p * 16 * ROWB);
#pragma unroll
            for (int mt = 0; mt < 2; mt++) {
                mma16816(acc[mt][2*p+0], ah[mt], bh4 + 0);
                mma16816(acc[mt][2*p+0], ah[mt], bl4 + 0);
                mma16816(acc[mt][2*p+0], al[mt], bh4 + 0);
                mma16816(acc[mt][2*p+1], ah[mt], bh4 + 2);
                mma16816(acc[mt][2*p+1], ah[mt], bl4 + 2);
                mma16816(acc[mt][2*p+1], al[mt], bh4 + 2);
            }
        }
        __syncthreads();
    }

    const int g = lane >> 2, qd = lane & 3;
#pragma unroll
    for (int mt = 0; mt < 2; mt++) {
        const int rowg = m0 + wm * 32 + mt * 16 + g;
#pragma unroll
        for (int nt = 0; nt < 8; nt++) {
            const int colg = n0 + wn * 64 + nt * 8 + qd * 2;
            const float b0 = bias[colg], b1 = bias[colg + 1];
            float2 o0 = make_float2(acc[mt][nt][0] + b0, acc[mt][nt][1] + b1);
            float2 o1 = make_float2(acc[mt][nt][2] + b0, acc[mt][nt][3] + b1);
            *(float2*)(C + (size_t)rowg * ldc + colg)       = o0;
            *(float2*)(C + (size_t)(rowg + 8) * ldc + colg) = o1;
        }
    }
}

__global__ __launch_bounds__(256)
void tc_gemm1(const __nv_bfloat16* __restrict__ a0, const __nv_bfloat16* __restrict__ a1,
              const __nv_bfloat16* __restrict__ w0, const __nv_bfloat16* __restrict__ w1,
              const float* __restrict__ b, float* __restrict__ C)
{
    tc_gemm_body(a0, a1, w0, w1, b, C, blockIdx.y * 128, blockIdx.x * 128, DMODEL);
}

// ======================= score kernel (attn phase 1, S -> gmem) ==============
#define TQ 16
#define KT 512
#define ATHREADS 512
#define NCC (SEQ / KT * 2)          // 8 chunk-iterations

// smem: Qs[16*64] | Ks[512*32 swizzled]  = 68 KB -> 3 CTAs/SM
#define SCORE_SMEM_BYTES ((TQ*64 + KT*32) * 4)

__global__ __launch_bounds__(ATHREADS)
void score_kernel(const float* __restrict__ Q, const float* __restrict__ K,
                  float* __restrict__ S)
{
    extern __shared__ char smraw[];
    float* Qs = (float*)smraw;
    float* Ks = Qs + TQ * 64;                 // 512 rows x 32 floats, swizzled

    const int tid = threadIdx.x;
    const int qt  = blockIdx.x;
    const int bh  = blockIdx.y;
    const int b   = bh >> 4, h = bh & 15;
    const int q0  = qt * TQ;

    const float* Qbase = Q + ((size_t)b * SEQ + q0) * DMODEL + h * HDIM;
    const float* Kbase = K + ((size_t)b * SEQ) * DMODEL + h * HDIM;
    float* Sbase = S + ((size_t)bh * SEQ + q0) * SEQ;

    if (tid < 256) {
        int row = tid >> 4, c4 = tid & 15;
        *(float4*)(Qs + row * 64 + c4 * 4) =
            *(const float4*)(Qbase + (size_t)row * DMODEL + c4 * 4);
    }

    const int kq  = tid & 127;
    const int qg  = tid >> 7;
    const int swz = kq & 7;

    const int prow = tid >> 3;
    const int pd4  = tid & 7;

    float4 st[8];
#pragma unroll
    for (int i = 0; i < 8; i++) {
        int row = i * 64 + prow;
        st[i] = *(const float4*)(Kbase + (size_t)row * DMODEL + pd4 * 4);
    }

    ull acc2[4][4];

    for (int cc = 0; cc < NCC; cc++) {
        const int ch = cc & 1;
        const int kb = (cc >> 1) * KT;

        __syncthreads();
#pragma unroll
        for (int i = 0; i < 8; i++) {
            int row = i * 64 + prow;
            *(float4*)(Ks + row * 32 + ((pd4 ^ ((row >> 2) & 7)) << 2)) = st[i];
        }
        if (cc + 1 < NCC) {
            const int nch = (cc + 1) & 1;
            const int nkb = ((cc + 1) >> 1) * KT;
#pragma unroll
            for (int i = 0; i < 8; i++) {
                int row = i * 64 + prow;
                st[i] = *(const float4*)(Kbase + (size_t)(nkb + row) * DMODEL
                                         + nch * 32 + pd4 * 4);
            }
        }
        __syncthreads();

        if (ch == 0) {
#pragma unroll
            for (int j = 0; j < 4; j++)
#pragma unroll
                for (int i = 0; i < 4; i++) acc2[j][i] = 0ull;
        }

#pragma unroll
        for (int d4 = 0; d4 < 8; d4++) {
            f4u kv[4];
#pragma unroll
            for (int i = 0; i < 4; i++)
                kv[i].f = *(float4*)(Ks + (kq * 4 + i) * 32 + ((d4 ^ swz) << 2));
#pragma unroll
            for (int j = 0; j < 4; j++) {
                f4u qv;
                qv.f = *(float4*)(Qs + (qg * 4 + j) * 64 + ch * 32 + (d4 << 2));
#pragma unroll
                for (int i = 0; i < 4; i++) {
                    ffma2(acc2[j][i], qv.u[0], kv[i].u[0]);
                    ffma2(acc2[j][i], qv.u[1], kv[i].u[1]);
                }
            }
        }

        if (ch == 1) {
#pragma unroll
            for (int j = 0; j < 4; j++) {
                float2 r0 = up2(acc2[j][0]), r1 = up2(acc2[j][1]);
                float2 r2 = up2(acc2[j][2]), r3 = up2(acc2[j][3]);
                float4 o = make_float4((r0.x + r0.y) * 0.125f, (r1.x + r1.y) * 0.125f,
                                       (r2.x + r2.y) * 0.125f, (r3.x + r3.y) * 0.125f);
                *(float4*)(Sbase + (size_t)(qg * 4 + j) * SEQ + kb + kq * 4) = o;
            }
        }
    }
}

// ======================= select kernel (attn phase 2, S from gmem) ===========
__device__ __forceinline__ unsigned fkey(float x) {
    unsigned u = __float_as_uint(x);
    return (u & 0x80000000u) ? ~u : (u | 0x80000000u);
}
__device__ __forceinline__ float unfkey(unsigned k) {
    unsigned u = (k & 0x80000000u) ? (k ^ 0x80000000u) : ~k;
    return __uint_as_float(u);
}

__device__ unsigned radix_select(const float* __restrict__ Srow,
                                 unsigned* __restrict__ myhist, int lane)
{
    unsigned prefix = 0;
    int remaining = U_TOP;
    for (int pass = 0; pass < 4; pass++) {
        const int shift = 24 - pass * 8;
#pragma unroll
        for (int j = 0; j < 8; j++) myhist[lane * 8 + j] = 0;
        __syncwarp();
        for (int i = lane; i < SEQ; i += 32) {
            unsigned key = fkey(Srow[i]);
            bool ok = (pass == 0) || ((key >> (shift + 8)) == prefix);
            if (ok) atomicAdd(&myhist[(key >> shift) & 255], 1u);
        }
        __syncwarp();
        unsigned psum = 0;
#pragma unroll
        for (int j = 0; j < 8; j++) psum += myhist[lane * 8 + j];
        unsigned c = psum;
#pragma unroll
        for (int off = 1; off < 32; off <<= 1) {
            unsigned o = __shfl_down_sync(0xffffffffu, c, off);
            if (lane + off < 32) c += o;
        }
        unsigned mk = __ballot_sync(0xffffffffu, c >= (unsigned)remaining);
        int lsel = 31 - __clz(mk);
        int digit = 0, newrem = remaining;
        if (lane == lsel) {
            unsigned cum = c - psum;
            for (int j = 7; j >= 0; j--) {
                unsigned hv = myhist[lsel * 8 + j];
                cum += hv;
                if (cum >= (unsigned)remaining) {
                    digit = lsel * 8 + j;
                    newrem = remaining - (int)(cum - hv);
                    break;
                }
            }
        }
        digit  = __shfl_sync(0xffffffffu, digit, lsel);
        newrem = __shfl_sync(0xffffffffu, newrem, lsel);
        prefix = (prefix << 8) | (unsigned)digit;
        remaining = newrem;
        __syncwarp();
    }
    return prefix;
}

__global__ __launch_bounds__(256)
void select_kernel(const float* __restrict__ S, const float* __restrict__ V,
                   float* __restrict__ ctx)
{
    __shared__ unsigned wbuf[8 * WBU];   // 15.4 KB

    const int tid  = threadIdx.x;
    const int lane = tid & 31, wid = tid >> 5;
    const unsigned lmlt = (1u << lane) - 1u;

    const int rr = blockIdx.x * 8 + wid;      // global score row 0..65535
    const int bh = rr >> 11;                  // row / 2048
    const int q  = rr & 2047;
    const int b  = bh >> 4, h = bh & 15;

    const float* Srow  = S + (size_t)rr * SEQ;
    const float* Vbase = V + ((size_t)b * SEQ) * DMODEL + h * HDIM;

    unsigned*       chk = wbuf + wid * WBU;
    unsigned short* chi = (unsigned short*)(chk + CCAP);
    unsigned*       myhist = chk;

    float lm = -1e30f;
    for (int i = lane; i < SEQ; i += 32) lm = fmaxf(lm, Srow[i]);
    float m = lm, tmin = lm;
#pragma unroll
    for (int off = 16; off; off >>= 1) {
        m    = fmaxf(m,    __shfl_xor_sync(0xffffffffu, m,    off));
        tmin = fminf(tmin, __shfl_xor_sync(0xffffffffu, tmin, off));
    }
    const unsigned Tk = fkey(tmin);

    int cnt = 0;
    for (int base = 0; base < SEQ; base += 32) {
        int i = base + lane;
        unsigned key = fkey(Srow[i]);
        bool kp = key >= Tk;
        unsigned bm = __ballot_sync(0xffffffffu, kp);
        if (kp) {
            int pos = cnt + __popc(bm & lmlt);
            if (pos < CCAP) { chk[pos] = key; chi[pos] = (unsigned short)i; }
        }
        cnt += __popc(bm);
    }
    __syncwarp();

    const bool okc = (cnt >= U_TOP && cnt <= CCAP);
    unsigned kth;
    if (okc) {
        unsigned ck[10];
#pragma unroll
        for (int t = 0; t < 10; t++) {
            int p = lane + t * 32;
            ck[t] = (p < cnt) ? chk[p] : 0u;
        }
        unsigned lo = Tk, hi = fkey(m);
        while (lo < hi) {
            unsigned mid = lo + ((hi - lo + 1) >> 1);
            int c = 0;
#pragma unroll
            for (int t = 0; t < 10; t++) c += (ck[t] >= mid) ? 1 : 0;
            c = __reduce_add_sync(0xffffffffu, c);
            if (c >= U_TOP) lo = mid; else hi = mid - 1;
        }
        kth = lo;
    } else {
        kth = radix_select(Srow, myhist, lane);
    }

    float lsum = 0.f;
    int nk = 0;
    if (okc) {
        for (int base = 0; base < cnt; base += 32) {
            int p = base + lane;
            unsigned key = (p < cnt) ? chk[p] : 0u;
            int idx      = (p < cnt) ? (int)chi[p] : 0;
            __syncwarp();
            bool kp = (p < cnt) && (key >= kth);
            unsigned bm = __ballot_sync(0xffffffffu, kp);
            if (kp) {
                float w = __expf(unfkey(key) - m);
                lsum += w;
                int pos = nk + __popc(bm & lmlt);
                chi[pos] = (unsigned short)idx;
                chk[pos] = __float_as_uint(w);
            }
            nk += __popc(bm);
        }
    } else {
        for (int base = 0; base < SEQ; base += 32) {
            int i = base + lane;
            float s = Srow[i];
            bool kp = fkey(s) >= kth;
            unsigned bm = __ballot_sync(0xffffffffu, kp);
            if (kp) {
                float w = __expf(s - m);
                lsum += w;
                int pos = nk + __popc(bm & lmlt);
                if (pos < CCAP) { chi[pos] = (unsigned short)i; chk[pos] = __float_as_uint(w); }
            }
            nk += __popc(bm);
        }
    }
    __syncwarp();
#pragma unroll
    for (int off = 16; off; off >>= 1)
        lsum += __shfl_xor_sync(0xffffffffu, lsum, off);
    const float scale = 1.f / lsum;

    float c0 = 0.f, c1 = 0.f;
    if (nk <= CCAP) {
        for (int j = 0; j < nk; j++) {
            int kkidx = (int)chi[j];
            float w = __uint_as_float(chk[j]);
            const float* vr = Vbase + (size_t)kkidx * DMODEL;
            c0 += w * vr[lane];
            c1 += w * vr[lane + 32];
        }
    } else {
        for (int i = 0; i < SEQ; i++) {
            float s = Srow[i];
            if (fkey(s) >= kth) {
                float w = __expf(s - m);
                const float* vr = Vbase + (size_t)i * DMODEL;
                c0 += w * vr[lane];
                c1 += w * vr[lane + 32];
            }
        }
    }
    float* orow = ctx + ((size_t)b * SEQ + q) * DMODEL + h * HDIM;
    orow[lane]      = c0 * scale;
    orow[lane + 32] = c1 * scale;
}

// ---------------- launch ----------------------------------------------------
extern "C" void kernel_launch(void* const* d_in, const int* in_sizes, int n_in,
                              void* d_out, int out_size)
{
    const float* x  = (const float*)d_in[0];
    const float* Wq = (const float*)d_in[1];
    const float* bq = (const float*)d_in[2];
    const float* Wk = (const float*)d_in[3];
    const float* bk = (const float*)d_in[4];
    const float* Wv = (const float*)d_in[5];
    const float* bv = (const float*)d_in[6];
    const float* Wo = (const float*)d_in[7];
    const float* bo = (const float*)d_in[8];
    float* out = (float*)d_out;

    float *Q, *K, *V, *C, *S;
    cudaGetSymbolAddress((void**)&Q, g_Q);
    cudaGetSymbolAddress((void**)&K, g_Kp);
    cudaGetSymbolAddress((void**)&V, g_Vp);
    cudaGetSymbolAddress((void**)&C, g_ctx);
    cudaGetSymbolAddress((void**)&S, g_S);
    __nv_bfloat16 *xh,*xl,*ch,*cl,*wvh,*wvl,*woh,*wol;
    cudaGetSymbolAddress((void**)&xh, g_xh);   cudaGetSymbolAddress((void**)&xl, g_xl);
    cudaGetSymbolAddress((void**)&ch, g_ch);   cudaGetSymbolAddress((void**)&cl, g_cl);
    cudaGetSymbolAddress((void**)&wvh, g_wvh); cudaGetSymbolAddress((void**)&wvl, g_wvl);
    cudaGetSymbolAddress((void**)&woh, g_woh); cudaGetSymbolAddress((void**)&wol, g_wol);

    // Q,K: exact fp32 FFMA2 pipelined path (selection-critical)
    qk_gemm<<<dim3(DMODEL / GBN, ROWS / GBM, 2), 256>>>(x, Wq, bq, Q, Wk, bk, K);

    // V: HMMA bf16x3 (precision-insensitive, measured fast)
    cvt_split<<<1024, 256>>>(x,  xh,  xl,  ROWS*DMODEL/4);
    cvt_split<<<512, 256>>>(Wv, wvh, wvl, DMODEL*DMODEL/4);
    cvt_split<<<512, 256>>>(Wo, woh, wol, DMODEL*DMODEL/4);
    tc_gemm1<<<dim3(DMODEL/128, ROWS/128), 256>>>(xh, xl, wvh, wvl, bv, V);

    cudaFuncSetAttribute(score_kernel, cudaFuncAttributeMaxDynamicSharedMemorySize,
                         SCORE_SMEM_BYTES);
    score_kernel<<<dim3(SEQ / TQ, BH), ATHREADS, SCORE_SMEM_BYTES>>>(Q, K, S);

    select_kernel<<<SROWS / 8, 256>>>(S, V, C);

    cvt_split<<<1024, 256>>>(C, ch, cl, ROWS*DMODEL/4);
    tc_gemm1<<<dim3(DMODEL/128, ROWS/128), 256>>>(ch, cl, woh, wol, bo, out);
}